// round 7
// baseline (speedup 1.0000x reference)
#include <cuda_runtime.h>
#include <math.h>

#define LL 4096
#define DM 128
#define DI 256
#define DS 16
#define EPS 1e-5f

// ---------------- scratch (static device allocations; allowed) ----------------
__device__ float g_xn   [2*2*LL*DM];     // [f][b][l][c]
__device__ float g_xz   [4*512*LL];      // [f*2+b][d2][l]
__device__ float g_xzd  [12*512*LL];     // [(f*3+dir)*2+b][d2][t]  (dir-ordered)
__device__ float g_xcv_tm[12*LL*DI];     // [z][t][d]
__device__ float g_xcv_dm[12*DI*LL];     // [z][d][t]
__device__ float g_dbl  [12*LL*40];      // [z][t][r]
__device__ float g_dt   [12*DI*LL];      // [z][d][t]
__device__ float g_ydir [12*DI*LL];      // [z][d][t]
__device__ float g_ycomb[4*DI*LL];       // [f*2+b][d][l]
__device__ float g_feat [4*DM*LL];       // [f*2+b][c][l]
__device__ float g_dp   [2*DM*DM];
__device__ float g_res  [2*DM*LL];
__device__ float g_bnmu [DM];
__device__ float g_bnrv [DM];

// ---------------- layernorm over channels: x[b,c,l] -> xn[f,b,l,c] ------------
__global__ void k_ln(const float* __restrict__ x1, const float* __restrict__ x2,
                     const float* __restrict__ lg, const float* __restrict__ lb)
{
    __shared__ float s[DM][33];
    __shared__ float mu_s[32], rv_s[32];
    int f = blockIdx.z, b = blockIdx.y, l0 = blockIdx.x*32, tid = threadIdx.x;
    const float* x = (f==0 ? x1 : x2) + (long)b*DM*LL;
    for (int idx=tid; idx<DM*32; idx+=256){
        int c = idx>>5, li = idx&31;
        s[c][li] = x[(long)c*LL + l0+li];
    }
    __syncthreads();
    if (tid < 32){
        float sum=0.f, sq=0.f;
        #pragma unroll 8
        for (int c=0;c<DM;c++){ float v=s[c][tid]; sum+=v; sq+=v*v; }
        float mu = sum*(1.f/DM);
        float var = sq*(1.f/DM) - mu*mu;
        mu_s[tid]=mu; rv_s[tid]=rsqrtf(var+EPS);
    }
    __syncthreads();
    float* outp = g_xn + ((long)(f*2+b)*LL + l0)*DM;
    for (int idx=tid; idx<32*DM; idx+=256){
        int li = idx>>7, c = idx&127;
        outp[(long)li*DM + c] = (s[c][li]-mu_s[li])*rv_s[li]*lg[c] + lb[c];
    }
}

// ---------------- C[M,N] = A[M,K] * B[N,K]^T  (both K-contiguous) -------------
__global__ void gemm_nt(const float* __restrict__ A, const float* __restrict__ B,
                        float* __restrict__ C, int M,int N,int K,
                        long aS, long bS, int bDiv, int bMod, long cS)
{
    int z = blockIdx.z;
    A += (long)z*aS;
    B += (long)((z/bDiv)%bMod)*bS;
    C += (long)z*cS;
    int tx=threadIdx.x, ty=threadIdx.y;
    int n0 = blockIdx.x*32, m0 = blockIdx.y*32;
    __shared__ float As[32][33], Bs[32][33];
    float acc[4]={0.f,0.f,0.f,0.f};
    for (int k0=0;k0<K;k0+=32){
        #pragma unroll
        for (int r=0;r<4;r++){
            int m = m0+ty+8*r;
            As[ty+8*r][tx] = A[(long)m*K + k0+tx];
            int n = n0+ty+8*r;
            Bs[ty+8*r][tx] = (n<N)? B[(long)n*K + k0+tx] : 0.f;
        }
        __syncthreads();
        #pragma unroll
        for (int kk=0;kk<32;kk++){
            float bv = Bs[tx][kk];
            #pragma unroll
            for (int r=0;r<4;r++) acc[r] += As[ty+8*r][kk]*bv;
        }
        __syncthreads();
    }
    int n = n0+tx;
    if (n<N){
        #pragma unroll
        for (int r=0;r<4;r++) C[(long)(m0+ty+8*r)*N + n] = acc[r];
    }
}

// ---------------- C[M,N] = A[M,K] * B[K,N]  (A K-contig, B N-contig) ----------
__global__ void gemm_nn(const float* __restrict__ A, const float* __restrict__ B,
                        float* __restrict__ C, int M,int N,int K,
                        long aS, long bS, int bDiv, int bMod, long cS)
{
    int z = blockIdx.z;
    A += (long)z*aS;
    B += (long)((z/bDiv)%bMod)*bS;
    C += (long)z*cS;
    int tx=threadIdx.x, ty=threadIdx.y;
    int n0 = blockIdx.x*32, m0 = blockIdx.y*32;
    __shared__ float As[32][33], Bs[32][33];
    float acc[4]={0.f,0.f,0.f,0.f};
    for (int k0=0;k0<K;k0+=32){
        #pragma unroll
        for (int r=0;r<4;r++){
            As[ty+8*r][tx] = A[(long)(m0+ty+8*r)*K + k0+tx];
            Bs[ty+8*r][tx] = B[(long)(k0+ty+8*r)*N + n0+tx];
        }
        __syncthreads();
        #pragma unroll
        for (int kk=0;kk<32;kk++){
            float bv = Bs[kk][tx];
            #pragma unroll
            for (int r=0;r<4;r++) acc[r] += As[ty+8*r][kk]*bv;
        }
        __syncthreads();
    }
    #pragma unroll
    for (int r=0;r<4;r++) C[(long)(m0+ty+8*r)*N + n0+tx] = acc[r];
}

// ---------------- direction remap: xz -> xzd (identity / flip / 64x64 T) ------
__global__ void k_remap()
{
    int z = blockIdx.z;
    int dir = (z%6)>>1;
    int fb  = (z/6)*2 + (z&1);
    const float* src = g_xz  + (long)fb*512*LL;
    float*       dst = g_xzd + (long)z *512*LL;
    int d = blockIdx.y, tid = threadIdx.x;
    __shared__ float s[32][33];
    if (dir==0){
        const float4* s4 = (const float4*)(src + (long)d*LL + blockIdx.x*1024);
        float4*       d4 = (float4*)      (dst + (long)d*LL + blockIdx.x*1024);
        d4[tid] = s4[tid];
    } else if (dir==1){
        int t = blockIdx.x*1024 + tid*4;
        const float* sr = src + (long)d*LL;
        float*       dw = dst + (long)d*LL;
        #pragma unroll
        for (int j=0;j<4;j++) dw[t+j] = sr[LL-1-(t+j)];
    } else {
        int a0 = (blockIdx.x&1)*32, b0 = (blockIdx.x>>1)*32;
        const float* sr = src + (long)d*LL;
        float*       dw = dst + (long)d*LL;
        #pragma unroll
        for (int q=0;q<4;q++){
            int idx = tid + q*256;
            int bb = idx>>5, aa = idx&31;
            s[bb][aa] = sr[(b0+bb)*64 + a0+aa];
        }
        __syncthreads();
        #pragma unroll
        for (int q=0;q<4;q++){
            int idx = tid + q*256;
            int aa = idx>>5, bb = idx&31;
            dw[(a0+aa)*64 + b0+bb] = s[bb][aa];
        }
    }
}

// ---------------- causal depthwise conv (DC=4) + silu; write both layouts -----
__global__ void k_conv(const float* __restrict__ cw, const float* __restrict__ cb)
{
    int z = blockIdx.z;
    int dir = (z%6)>>1;
    int t0 = blockIdx.x*32, d0 = blockIdx.y*32;
    int tx = threadIdx.x, ty = threadIdx.y;
    const float* xin = g_xzd + (long)z*512*LL;
    __shared__ float s[32][33];
    int t = t0+tx;
    #pragma unroll
    for (int r=0;r<4;r++){
        int d = d0+ty+8*r;
        const float* w = cw + dir*DI*4 + d*4;
        float acc = cb[dir*DI + d];
        const float* row = xin + (long)d*LL;
        #pragma unroll
        for (int k=0;k<4;k++){
            int ts = t-3+k;
            float xv = (ts>=0)? row[ts] : 0.f;
            acc += w[k]*xv;
        }
        float sv = acc / (1.f + __expf(-acc));
        s[ty+8*r][tx] = sv;
        g_xcv_dm[(long)z*DI*LL + (long)d*LL + t] = sv;
    }
    __syncthreads();
    #pragma unroll
    for (int r=0;r<4;r++){
        int tt = t0+ty+8*r;
        g_xcv_tm[(long)z*LL*DI + (long)tt*DI + d0+tx] = s[tx][ty+8*r];
    }
}

// ---------------- dt = softplus(dbl[:,:8] @ dpw^T + dpb) ----------------------
__global__ void k_dtproj(const float* __restrict__ dpw, const float* __restrict__ dpb)
{
    int z = blockIdx.z, d = blockIdx.y;
    int dir = (z%6)>>1;
    int t = blockIdx.x*256 + threadIdx.x;
    const float* row = g_dbl + (long)z*LL*40 + (long)t*40;
    const float* w   = dpw + dir*DI*8 + d*8;
    float acc = dpb[dir*DI + d];
    #pragma unroll
    for (int r=0;r<8;r++) acc += row[r]*w[r];
    float sp = fmaxf(acc,0.f) + log1pf(__expf(-fabsf(acc)));
    g_dt[(long)z*DI*LL + (long)d*LL + t] = sp;
}

// ---------------- selective scan: 16 lanes per (b,d), shfl-reduce y -----------
__global__ void k_scan(const float* __restrict__ A_log, const float* __restrict__ Dp)
{
    int z = blockIdx.y;
    int dir = (z%6)>>1;
    int d0 = blockIdx.x*16;
    int tid = threadIdx.x;
    int warp = tid>>5, lane = tid&31;
    int g = warp*2 + (lane>>4);
    int n = lane&15;
    int d = d0+g;
    float An = -__expf(A_log[(long)(dir*DI + d)*DS + n]);

    const float* dtB  = g_dt     + (long)z*DI*LL;
    const float* xB   = g_xcv_dm + (long)z*DI*LL;
    const float* dblB = g_dbl    + (long)z*LL*40;
    const float* zB   = g_xzd    + (long)z*512*LL + (long)DI*LL;
    float* yB = g_ydir + (long)z*DI*LL;

    __shared__ float s_dt[16][129], s_x[16][129], s_y[16][129];
    __shared__ float s_Bc[128][16], s_Cc[128][16];
    float h = 0.f;

    for (int c0=0;c0<LL;c0+=128){
        for (int idx=tid; idx<16*128; idx+=256){
            int r = idx>>7, cc = idx&127;
            s_dt[r][cc] = dtB[(long)(d0+r)*LL + c0+cc];
            s_x[r][cc]  = xB [(long)(d0+r)*LL + c0+cc];
        }
        for (int idx=tid; idx<128*16; idx+=256){
            int tt = idx>>4, nn = idx&15;
            const float* row = dblB + (long)(c0+tt)*40;
            s_Bc[tt][nn] = row[8+nn];
            s_Cc[tt][nn] = row[24+nn];
        }
        __syncthreads();
        #pragma unroll 4
        for (int t=0;t<128;t++){
            float dtv = s_dt[g][t];
            float xv  = s_x [g][t];
            float da = __expf(dtv*An);
            h = da*h + (dtv*xv)*s_Bc[t][n];
            float p = h*s_Cc[t][n];
            p += __shfl_xor_sync(0xffffffffu, p, 8);
            p += __shfl_xor_sync(0xffffffffu, p, 4);
            p += __shfl_xor_sync(0xffffffffu, p, 2);
            p += __shfl_xor_sync(0xffffffffu, p, 1);
            if (n==0) s_y[g][t] = p;
        }
        __syncthreads();
        for (int idx=tid; idx<16*128; idx+=256){
            int r = idx>>7, cc = idx&127;
            int dd = d0+r; int tt = c0+cc;
            float zv = zB[(long)dd*LL + tt];
            float sz = zv / (1.f + __expf(-zv));
            yB[(long)dd*LL + tt] = (s_y[r][cc] + Dp[dir*DI+dd]*s_x[r][cc]) * sz;
        }
        __syncthreads();
    }
}

// ---------------- combine 3 directions (fwd + flip + 64x64 transpose) ---------
__global__ void k_combine()
{
    int z2 = blockIdx.z, d = blockIdx.y;
    int f = z2>>1, b = z2&1;
    long off0 = ((long)((f*3+0)*2+b)*DI + d)*LL;
    long off1 = ((long)((f*3+1)*2+b)*DI + d)*LL;
    long off2 = ((long)((f*3+2)*2+b)*DI + d)*LL;
    long offo = ((long)z2*DI + d)*LL;
    int i0 = (blockIdx.x&1)*32, j0 = (blockIdx.x>>1)*32;
    int tx=threadIdx.x, ty=threadIdx.y;
    __shared__ float s[32][33];
    #pragma unroll
    for (int r=0;r<4;r++){
        int jj = ty+8*r;
        s[jj][tx] = g_ydir[off2 + (j0+jj)*64 + i0+tx];
    }
    __syncthreads();
    #pragma unroll
    for (int r=0;r<4;r++){
        int ii = ty+8*r;
        int l = (i0+ii)*64 + j0+tx;
        g_ycomb[offo + l] = g_ydir[off0 + l] + g_ydir[off1 + (LL-1-l)] + s[tx][ii];
    }
}

// ---------------- res[c][l] -> out flat (l*128 + c), via tile transpose -------
__global__ void k_resremap(float* __restrict__ outp)
{
    int b = blockIdx.z, c0 = blockIdx.y*32, l0 = blockIdx.x*32;
    int tx=threadIdx.x, ty=threadIdx.y;
    __shared__ float s[32][33];
    #pragma unroll
    for (int r=0;r<4;r++){
        int cl = ty+8*r;
        s[cl][tx] = g_res[(long)b*DM*LL + (long)(c0+cl)*LL + l0+tx];
    }
    __syncthreads();
    #pragma unroll
    for (int r=0;r<4;r++){
        int ll = ty+8*r;
        outp[(long)b*DM*LL + (long)(l0+ll)*DM + c0+tx] = s[tx][ll];
    }
}

// ---------------- batchnorm over (b,h,w) per channel --------------------------
__global__ void k_bnstats(const float* __restrict__ outp)
{
    int cc = blockIdx.x, tid = threadIdx.x;
    __shared__ float ss[256], sq[256];
    float a=0.f, q=0.f;
    for (int i=tid;i<2*LL;i+=256){
        float v = outp[(long)(i>>12)*DM*LL + (long)cc*LL + (i&(LL-1))];
        a+=v; q+=v*v;
    }
    ss[tid]=a; sq[tid]=q;
    __syncthreads();
    for (int st=128; st>0; st>>=1){
        if (tid<st){ ss[tid]+=ss[tid+st]; sq[tid]+=sq[tid+st]; }
        __syncthreads();
    }
    if (tid==0){
        float mu = ss[0]*(1.f/(2*LL));
        float var = sq[0]*(1.f/(2*LL)) - mu*mu;
        g_bnmu[cc]=mu; g_bnrv[cc]=rsqrtf(var+EPS);
    }
}

__global__ void k_bnapply(float* __restrict__ outp, const float* __restrict__ bg,
                          const float* __restrict__ bb)
{
    long gi = (long)blockIdx.x*256 + threadIdx.x;
    int cc = (int)((gi>>12)&127);
    outp[gi] = (outp[gi]-g_bnmu[cc])*g_bnrv[cc]*bg[cc] + bb[cc];
}

// ---------------- launcher ----------------------------------------------------
extern "C" void kernel_launch(void* const* d_in, const int* in_sizes, int n_in,
                              void* d_out, int out_size)
{
    const float* x1        = (const float*)d_in[0];
    const float* x2        = (const float*)d_in[1];
    const float* ln_g      = (const float*)d_in[2];
    const float* ln_b      = (const float*)d_in[3];
    const float* in_proj_w = (const float*)d_in[4];
    const float* conv_w    = (const float*)d_in[5];
    const float* conv_b    = (const float*)d_in[6];
    const float* xproj_w   = (const float*)d_in[7];
    const float* dtproj_w  = (const float*)d_in[8];
    const float* dtproj_b  = (const float*)d_in[9];
    const float* A_log     = (const float*)d_in[10];
    const float* Dvec      = (const float*)d_in[11];
    const float* out_proj_w= (const float*)d_in[12];
    const float* bn_g      = (const float*)d_in[13];
    const float* bn_b      = (const float*)d_in[14];
    float* outp = (float*)d_out;

    float *p_xn,*p_xz,*p_tm,*p_dbl,*p_ycomb,*p_feat,*p_dp,*p_res;
    cudaGetSymbolAddress((void**)&p_xn,   g_xn);
    cudaGetSymbolAddress((void**)&p_xz,   g_xz);
    cudaGetSymbolAddress((void**)&p_tm,   g_xcv_tm);
    cudaGetSymbolAddress((void**)&p_dbl,  g_dbl);
    cudaGetSymbolAddress((void**)&p_ycomb,g_ycomb);
    cudaGetSymbolAddress((void**)&p_feat, g_feat);
    cudaGetSymbolAddress((void**)&p_dp,   g_dp);
    cudaGetSymbolAddress((void**)&p_res,  g_res);

    dim3 blk(32,8);

    // 1. layernorm -> xn[f,b,l,c]
    k_ln<<<dim3(128,2,2),256>>>(x1,x2,ln_g,ln_b);
    // 2. in_proj: xz[fb,d2,l] = W(512x128) * xn^T
    gemm_nt<<<dim3(128,16,4),blk>>>(in_proj_w, p_xn, p_xz,
                                    512,4096,128, 0L,(long)LL*DM,1,4,(long)512*LL);
    // 3. direction remap
    k_remap<<<dim3(4,512,12),256>>>();
    // 4. causal conv + silu
    k_conv<<<dim3(128,8,12),blk>>>(conv_w, conv_b);
    // 5. xproj: dbl[z,t,40] = xcv_tm(4096x256) * xpw^T(40x256)
    gemm_nt<<<dim3(2,128,12),blk>>>(p_tm, xproj_w, p_dbl,
                                    4096,40,256,(long)LL*DI,40L*DI,2,3,(long)LL*40);
    // 6. dt projection + softplus
    k_dtproj<<<dim3(16,256,12),256>>>(dtproj_w, dtproj_b);
    // 7. selective scan + gate
    k_scan<<<dim3(16,12),256>>>(A_log, Dvec);
    // 8. combine 3 directions
    k_combine<<<dim3(4,256,4),blk>>>();
    // 9. out_proj: feat[fb,c,l] = opw(128x256) * ycomb(256xL)
    gemm_nn<<<dim3(128,4,4),blk>>>(out_proj_w, p_ycomb, p_feat,
                                   128,4096,256, 0L,(long)DI*LL,1,4,(long)DM*LL);
    // 10. dp[b,c,d] = A * Bf^T over L
    gemm_nt<<<dim3(4,4,2),blk>>>(p_feat, p_feat + 2L*DM*LL, p_dp,
                                 128,128,4096,(long)DM*LL,(long)DM*LL,1,2,(long)DM*DM);
    // 11. res[b,c,l] = dp * Bf
    gemm_nn<<<dim3(128,4,2),blk>>>(p_dp, p_feat + 2L*DM*LL, p_res,
                                   128,4096,128,(long)DM*DM,(long)DM*LL,1,2,(long)DM*LL);
    // 12. remap res -> out layout (b, c', h, w) == flat (l*128 + c)
    k_resremap<<<dim3(128,4,2),blk>>>(outp);
    // 13-14. batchnorm over (b,h,w)  (1,048,576 elements total -> 4096 blocks)
    k_bnstats<<<128,256>>>(outp);
    k_bnapply<<<4096,256>>>(outp, bn_g, bn_b);
}

// round 8
// speedup vs baseline: 1.5328x; 1.5328x over previous
#include <cuda_runtime.h>
#include <math.h>

#define LL 4096
#define DM 128
#define DI 256
#define DS 16
#define EPS 1e-5f

// ---------------- scratch (static device allocations; allowed) ----------------
__device__ float g_xn   [2*2*LL*DM];     // [f][b][l][c]
__device__ float g_xz   [4*512*LL];      // [f*2+b][d2][l]
__device__ float g_xzd  [12*512*LL];     // [(f*3+dir)*2+b][d2][t]
__device__ float g_xcv_dm[12*DI*LL];     // [z][d][t]
__device__ float g_dblT [12*40*LL];      // [z][r][t]   (transposed vs round 7)
__device__ float g_dt   [12*DI*LL];      // [z][d][t]
__device__ float g_ydir [12*DI*LL];      // [z][d][t]
__device__ float g_ycomb[4*DI*LL];       // [f*2+b][d][l]
__device__ float g_feat [4*DM*LL];       // [f*2+b][c][l]
__device__ float g_dpp  [32*DM*DM];      // split-K partials for dp
__device__ float g_dp   [2*DM*DM];
__device__ float g_res  [2*DM*LL];
__device__ float g_bnmu [DM];
__device__ float g_bnrv [DM];

// ---------------- layernorm over channels: x[b,c,l] -> xn[f,b,l,c] ------------
__global__ void k_ln(const float* __restrict__ x1, const float* __restrict__ x2,
                     const float* __restrict__ lg, const float* __restrict__ lb)
{
    __shared__ float s[DM][33];
    __shared__ float mu_s[32], rv_s[32];
    int f = blockIdx.z, b = blockIdx.y, l0 = blockIdx.x*32, tid = threadIdx.x;
    const float* x = (f==0 ? x1 : x2) + (long)b*DM*LL;
    for (int idx=tid; idx<DM*32; idx+=256){
        int c = idx>>5, li = idx&31;
        s[c][li] = x[(long)c*LL + l0+li];
    }
    __syncthreads();
    if (tid < 32){
        float sum=0.f, sq=0.f;
        #pragma unroll 8
        for (int c=0;c<DM;c++){ float v=s[c][tid]; sum+=v; sq+=v*v; }
        float mu = sum*(1.f/DM);
        float var = sq*(1.f/DM) - mu*mu;
        mu_s[tid]=mu; rv_s[tid]=rsqrtf(var+EPS);
    }
    __syncthreads();
    float* outp = g_xn + ((long)(f*2+b)*LL + l0)*DM;
    for (int idx=tid; idx<32*DM; idx+=256){
        int li = idx>>7, c = idx&127;
        outp[(long)li*DM + c] = (s[c][li]-mu_s[li])*rv_s[li]*lg[c] + lb[c];
    }
}

// ======== 64x64-tile SGEMM, 256 threads, 4x4 outputs/thread, K-tile 16 ========
// NT: C[M,N] = A[M,K] * B[N,K]^T  (A,B K-contiguous)
__global__ void gemm_nt64(const float* __restrict__ A, const float* __restrict__ B,
                          float* __restrict__ C, int M,int N,int K,
                          long aS,int aDiv,int aMod, long bS,int bDiv,int bMod, long cS)
{
    int z = blockIdx.z;
    A += (long)((z/aDiv)%aMod)*aS;
    B += (long)((z/bDiv)%bMod)*bS;
    C += (long)z*cS;
    int tid = threadIdx.x;
    int tx = tid&15, ty = tid>>4;
    int n0 = blockIdx.x*64, m0 = blockIdx.y*64;
    int lm = tid>>2, lk4 = (tid&3)*4;
    __shared__ float As[16][68], Bs[16][68];
    float acc[4][4] = {};
    bool am = (m0+lm) < M;
    bool bn = (n0+lm) < N;
    for (int k0=0;k0<K;k0+=16){
        float4 av = am ? *(const float4*)(A + (long)(m0+lm)*K + k0+lk4)
                       : make_float4(0.f,0.f,0.f,0.f);
        float4 bv = bn ? *(const float4*)(B + (long)(n0+lm)*K + k0+lk4)
                       : make_float4(0.f,0.f,0.f,0.f);
        As[lk4+0][lm]=av.x; As[lk4+1][lm]=av.y; As[lk4+2][lm]=av.z; As[lk4+3][lm]=av.w;
        Bs[lk4+0][lm]=bv.x; Bs[lk4+1][lm]=bv.y; Bs[lk4+2][lm]=bv.z; Bs[lk4+3][lm]=bv.w;
        __syncthreads();
        #pragma unroll
        for (int kk=0;kk<16;kk++){
            float4 a = *(const float4*)&As[kk][ty*4];
            float4 b = *(const float4*)&Bs[kk][tx*4];
            float aa[4]={a.x,a.y,a.z,a.w}, bb[4]={b.x,b.y,b.z,b.w};
            #pragma unroll
            for (int i=0;i<4;i++)
                #pragma unroll
                for (int j=0;j<4;j++) acc[i][j] += aa[i]*bb[j];
        }
        __syncthreads();
    }
    #pragma unroll
    for (int i=0;i<4;i++){
        int m = m0+ty*4+i;
        if (m < M){
            #pragma unroll
            for (int j=0;j<4;j++){
                int n = n0+tx*4+j;
                if (n < N) C[(long)m*N + n] = acc[i][j];
            }
        }
    }
}

// NN: C[M,N] = A[M,K] * B[K,N]  (A K-contig, B N-contig)
__global__ void gemm_nn64(const float* __restrict__ A, const float* __restrict__ B,
                          float* __restrict__ C, int M,int N,int K,
                          long aS,int aDiv,int aMod, long bS,int bDiv,int bMod, long cS)
{
    int z = blockIdx.z;
    A += (long)((z/aDiv)%aMod)*aS;
    B += (long)((z/bDiv)%bMod)*bS;
    C += (long)z*cS;
    int tid = threadIdx.x;
    int tx = tid&15, ty = tid>>4;
    int n0 = blockIdx.x*64, m0 = blockIdx.y*64;
    int lm = tid>>2, lk4 = (tid&3)*4;
    int bk = tid>>6, bn_i = tid&63;        // B loader: 4 k-rows of 64 n
    __shared__ float As[16][68], Bs[16][68];
    float acc[4][4] = {};
    bool am = (m0+lm) < M;
    bool bok = (n0+bn_i) < N;
    for (int k0=0;k0<K;k0+=16){
        float4 av = am ? *(const float4*)(A + (long)(m0+lm)*K + k0+lk4)
                       : make_float4(0.f,0.f,0.f,0.f);
        As[lk4+0][lm]=av.x; As[lk4+1][lm]=av.y; As[lk4+2][lm]=av.z; As[lk4+3][lm]=av.w;
        #pragma unroll
        for (int q=0;q<4;q++){
            int kr = bk + q*4;
            Bs[kr][bn_i] = bok ? B[(long)(k0+kr)*N + n0+bn_i] : 0.f;
        }
        __syncthreads();
        #pragma unroll
        for (int kk=0;kk<16;kk++){
            float4 a = *(const float4*)&As[kk][ty*4];
            float4 b = *(const float4*)&Bs[kk][tx*4];
            float aa[4]={a.x,a.y,a.z,a.w}, bb[4]={b.x,b.y,b.z,b.w};
            #pragma unroll
            for (int i=0;i<4;i++)
                #pragma unroll
                for (int j=0;j<4;j++) acc[i][j] += aa[i]*bb[j];
        }
        __syncthreads();
    }
    #pragma unroll
    for (int i=0;i<4;i++){
        int m = m0+ty*4+i;
        if (m < M){
            #pragma unroll
            for (int j=0;j<4;j++){
                int n = n0+tx*4+j;
                if (n < N) C[(long)m*N + n] = acc[i][j];
            }
        }
    }
}

// ---------------- split-K dp: dpp[b*16+ch][c][d] = A_chunk * Bf_chunk^T -------
__global__ void k_dp(const float* __restrict__ feat, float* __restrict__ dpp)
{
    int zz = blockIdx.z; int b = zz>>4, ch = zz&15;
    const float* A  = feat + (long)b    *DM*LL + ch*256;
    const float* Bp = feat + (long)(2+b)*DM*LL + ch*256;
    int tid = threadIdx.x;
    int tx = tid&15, ty = tid>>4;
    int n0 = blockIdx.x*64, m0 = blockIdx.y*64;
    int lm = tid>>2, lk4 = (tid&3)*4;
    __shared__ float As[16][68], Bs[16][68];
    float acc[4][4] = {};
    for (int k0=0;k0<256;k0+=16){
        float4 av = *(const float4*)(A  + (long)(m0+lm)*LL + k0+lk4);
        float4 bv = *(const float4*)(Bp + (long)(n0+lm)*LL + k0+lk4);
        As[lk4+0][lm]=av.x; As[lk4+1][lm]=av.y; As[lk4+2][lm]=av.z; As[lk4+3][lm]=av.w;
        Bs[lk4+0][lm]=bv.x; Bs[lk4+1][lm]=bv.y; Bs[lk4+2][lm]=bv.z; Bs[lk4+3][lm]=bv.w;
        __syncthreads();
        #pragma unroll
        for (int kk=0;kk<16;kk++){
            float4 a = *(const float4*)&As[kk][ty*4];
            float4 b = *(const float4*)&Bs[kk][tx*4];
            float aa[4]={a.x,a.y,a.z,a.w}, bb[4]={b.x,b.y,b.z,b.w};
            #pragma unroll
            for (int i=0;i<4;i++)
                #pragma unroll
                for (int j=0;j<4;j++) acc[i][j] += aa[i]*bb[j];
        }
        __syncthreads();
    }
    float* Cp = dpp + (long)zz*DM*DM;
    #pragma unroll
    for (int i=0;i<4;i++)
        #pragma unroll
        for (int j=0;j<4;j++)
            Cp[(long)(m0+ty*4+i)*DM + n0+tx*4+j] = acc[i][j];
}

__global__ void k_dpred()
{
    int i = blockIdx.x*256 + threadIdx.x;   // 0..32767
    int b = i>>14, j = i&16383;
    float s = 0.f;
    #pragma unroll
    for (int ch=0;ch<16;ch++) s += g_dpp[(long)(b*16+ch)*DM*DM + j];
    g_dp[(long)b*DM*DM + j] = s;
}

// ---------------- direction remap: xz -> xzd (identity / flip / 64x64 T) ------
__global__ void k_remap()
{
    int z = blockIdx.z;
    int dir = (z%6)>>1;
    int fb  = (z/6)*2 + (z&1);
    const float* src = g_xz  + (long)fb*512*LL;
    float*       dst = g_xzd + (long)z *512*LL;
    int d = blockIdx.y, tid = threadIdx.x;
    __shared__ float s[32][33];
    if (dir==0){
        const float4* s4 = (const float4*)(src + (long)d*LL + blockIdx.x*1024);
        float4*       d4 = (float4*)      (dst + (long)d*LL + blockIdx.x*1024);
        d4[tid] = s4[tid];
    } else if (dir==1){
        int t = blockIdx.x*1024 + tid*4;
        const float* sr = src + (long)d*LL;
        float*       dw = dst + (long)d*LL;
        #pragma unroll
        for (int j=0;j<4;j++) dw[t+j] = sr[LL-1-(t+j)];
    } else {
        int a0 = (blockIdx.x&1)*32, b0 = (blockIdx.x>>1)*32;
        const float* sr = src + (long)d*LL;
        float*       dw = dst + (long)d*LL;
        #pragma unroll
        for (int q=0;q<4;q++){
            int idx = tid + q*256;
            int bb = idx>>5, aa = idx&31;
            s[bb][aa] = sr[(b0+bb)*64 + a0+aa];
        }
        __syncthreads();
        #pragma unroll
        for (int q=0;q<4;q++){
            int idx = tid + q*256;
            int aa = idx>>5, bb = idx&31;
            dw[(a0+aa)*64 + b0+bb] = s[bb][aa];
        }
    }
}

// ---------------- causal depthwise conv (DC=4) + silu ([d][t] layout only) ----
__global__ void k_conv(const float* __restrict__ cw, const float* __restrict__ cb)
{
    int z = blockIdx.z;
    int dir = (z%6)>>1;
    int d = blockIdx.y;
    int t = blockIdx.x*256 + threadIdx.x;
    const float* row = g_xzd + (long)z*512*LL + (long)d*LL;
    const float* w = cw + (dir*DI + d)*4;
    float acc = cb[dir*DI + d];
    #pragma unroll
    for (int k=0;k<4;k++){
        int ts = t-3+k;
        float xv = (ts>=0)? row[ts] : 0.f;
        acc += w[k]*xv;
    }
    float sv = acc / (1.f + __expf(-acc));
    g_xcv_dm[(long)z*DI*LL + (long)d*LL + t] = sv;
}

// ---------------- dt = softplus(dblT[:8]^T @ dpw^T + dpb), coalesced ---------
__global__ void k_dtproj(const float* __restrict__ dpw, const float* __restrict__ dpb)
{
    int z = blockIdx.z, d = blockIdx.y;
    int dir = (z%6)>>1;
    int t = blockIdx.x*256 + threadIdx.x;
    const float* base = g_dblT + (long)z*40*LL;
    const float* w   = dpw + (dir*DI + d)*8;
    float acc = dpb[dir*DI + d];
    #pragma unroll
    for (int r=0;r<8;r++) acc += base[(long)r*LL + t]*w[r];
    float sp = fmaxf(acc,0.f) + log1pf(__expf(-fabsf(acc)));
    g_dt[(long)z*DI*LL + (long)d*LL + t] = sp;
}

// ---------------- selective scan: 16 lanes per (b,d), shfl-reduce y -----------
__global__ void k_scan(const float* __restrict__ A_log, const float* __restrict__ Dp)
{
    int z = blockIdx.y;
    int dir = (z%6)>>1;
    int d0 = blockIdx.x*16;
    int tid = threadIdx.x;
    int warp = tid>>5, lane = tid&31;
    int g = warp*2 + (lane>>4);
    int n = lane&15;
    int d = d0+g;
    float An = -__expf(A_log[(long)(dir*DI + d)*DS + n]);

    const float* dtB  = g_dt     + (long)z*DI*LL;
    const float* xB   = g_xcv_dm + (long)z*DI*LL;
    const float* dblT = g_dblT   + (long)z*40*LL;
    const float* zB   = g_xzd    + (long)z*512*LL + (long)DI*LL;
    float* yB = g_ydir + (long)z*DI*LL;

    __shared__ float s_dt[16][129], s_x[16][129], s_y[16][129];
    __shared__ float s_Bc[128][17], s_Cc[128][17];
    float h = 0.f;

    for (int c0=0;c0<LL;c0+=128){
        for (int idx=tid; idx<16*128; idx+=256){
            int r = idx>>7, cc = idx&127;
            s_dt[r][cc] = dtB[(long)(d0+r)*LL + c0+cc];
            s_x[r][cc]  = xB [(long)(d0+r)*LL + c0+cc];
        }
        for (int idx=tid; idx<16*128; idx+=256){
            int nn = idx>>7, tt = idx&127;
            s_Bc[tt][nn] = dblT[(long)(8+nn)*LL + c0+tt];
            s_Cc[tt][nn] = dblT[(long)(24+nn)*LL + c0+tt];
        }
        __syncthreads();
        #pragma unroll 4
        for (int t=0;t<128;t++){
            float dtv = s_dt[g][t];
            float xv  = s_x [g][t];
            float da = __expf(dtv*An);
            h = da*h + (dtv*xv)*s_Bc[t][n];
            float p = h*s_Cc[t][n];
            p += __shfl_xor_sync(0xffffffffu, p, 8);
            p += __shfl_xor_sync(0xffffffffu, p, 4);
            p += __shfl_xor_sync(0xffffffffu, p, 2);
            p += __shfl_xor_sync(0xffffffffu, p, 1);
            if (n==0) s_y[g][t] = p;
        }
        __syncthreads();
        for (int idx=tid; idx<16*128; idx+=256){
            int r = idx>>7, cc = idx&127;
            int dd = d0+r; int tt = c0+cc;
            float zv = zB[(long)dd*LL + tt];
            float sz = zv / (1.f + __expf(-zv));
            yB[(long)dd*LL + tt] = (s_y[r][cc] + Dp[dir*DI+dd]*s_x[r][cc]) * sz;
        }
        __syncthreads();
    }
}

// ---------------- combine 3 directions (fwd + flip + 64x64 transpose) ---------
__global__ void k_combine()
{
    int z2 = blockIdx.z, d = blockIdx.y;
    int f = z2>>1, b = z2&1;
    long off0 = ((long)((f*3+0)*2+b)*DI + d)*LL;
    long off1 = ((long)((f*3+1)*2+b)*DI + d)*LL;
    long off2 = ((long)((f*3+2)*2+b)*DI + d)*LL;
    long offo = ((long)z2*DI + d)*LL;
    int i0 = (blockIdx.x&1)*32, j0 = (blockIdx.x>>1)*32;
    int tx=threadIdx.x, ty=threadIdx.y;
    __shared__ float s[32][33];
    #pragma unroll
    for (int r=0;r<4;r++){
        int jj = ty+8*r;
        s[jj][tx] = g_ydir[off2 + (j0+jj)*64 + i0+tx];
    }
    __syncthreads();
    #pragma unroll
    for (int r=0;r<4;r++){
        int ii = ty+8*r;
        int l = (i0+ii)*64 + j0+tx;
        g_ycomb[offo + l] = g_ydir[off0 + l] + g_ydir[off1 + (LL-1-l)] + s[tx][ii];
    }
}

// ---------------- res[c][l] -> out flat (l*128 + c), via tile transpose -------
__global__ void k_resremap(float* __restrict__ outp)
{
    int b = blockIdx.z, c0 = blockIdx.y*32, l0 = blockIdx.x*32;
    int tx=threadIdx.x, ty=threadIdx.y;
    __shared__ float s[32][33];
    #pragma unroll
    for (int r=0;r<4;r++){
        int cl = ty+8*r;
        s[cl][tx] = g_res[(long)b*DM*LL + (long)(c0+cl)*LL + l0+tx];
    }
    __syncthreads();
    #pragma unroll
    for (int r=0;r<4;r++){
        int ll = ty+8*r;
        outp[(long)b*DM*LL + (long)(l0+ll)*DM + c0+tx] = s[tx][ll];
    }
}

// ---------------- batchnorm over (b,h,w) per channel --------------------------
__global__ void k_bnstats(const float* __restrict__ outp)
{
    int cc = blockIdx.x, tid = threadIdx.x;
    __shared__ float ss[256], sq[256];
    float a=0.f, q=0.f;
    for (int i=tid;i<2*LL;i+=256){
        float v = outp[(long)(i>>12)*DM*LL + (long)cc*LL + (i&(LL-1))];
        a+=v; q+=v*v;
    }
    ss[tid]=a; sq[tid]=q;
    __syncthreads();
    for (int st=128; st>0; st>>=1){
        if (tid<st){ ss[tid]+=ss[tid+st]; sq[tid]+=sq[tid+st]; }
        __syncthreads();
    }
    if (tid==0){
        float mu = ss[0]*(1.f/(2*LL));
        float var = sq[0]*(1.f/(2*LL)) - mu*mu;
        g_bnmu[cc]=mu; g_bnrv[cc]=rsqrtf(var+EPS);
    }
}

__global__ void k_bnapply(float* __restrict__ outp, const float* __restrict__ bg,
                          const float* __restrict__ bb)
{
    long gi = (long)blockIdx.x*256 + threadIdx.x;
    int cc = (int)((gi>>12)&127);
    outp[gi] = (outp[gi]-g_bnmu[cc])*g_bnrv[cc]*bg[cc] + bb[cc];
}

// ---------------- launcher ----------------------------------------------------
extern "C" void kernel_launch(void* const* d_in, const int* in_sizes, int n_in,
                              void* d_out, int out_size)
{
    const float* x1        = (const float*)d_in[0];
    const float* x2        = (const float*)d_in[1];
    const float* ln_g      = (const float*)d_in[2];
    const float* ln_b      = (const float*)d_in[3];
    const float* in_proj_w = (const float*)d_in[4];
    const float* conv_w    = (const float*)d_in[5];
    const float* conv_b    = (const float*)d_in[6];
    const float* xproj_w   = (const float*)d_in[7];
    const float* dtproj_w  = (const float*)d_in[8];
    const float* dtproj_b  = (const float*)d_in[9];
    const float* A_log     = (const float*)d_in[10];
    const float* Dvec      = (const float*)d_in[11];
    const float* out_proj_w= (const float*)d_in[12];
    const float* bn_g      = (const float*)d_in[13];
    const float* bn_b      = (const float*)d_in[14];
    float* outp = (float*)d_out;

    float *p_xn,*p_xz,*p_dm,*p_dblT,*p_ycomb,*p_feat,*p_dpp,*p_dp,*p_res;
    cudaGetSymbolAddress((void**)&p_xn,   g_xn);
    cudaGetSymbolAddress((void**)&p_xz,   g_xz);
    cudaGetSymbolAddress((void**)&p_dm,   g_xcv_dm);
    cudaGetSymbolAddress((void**)&p_dblT, g_dblT);
    cudaGetSymbolAddress((void**)&p_ycomb,g_ycomb);
    cudaGetSymbolAddress((void**)&p_feat, g_feat);
    cudaGetSymbolAddress((void**)&p_dpp,  g_dpp);
    cudaGetSymbolAddress((void**)&p_dp,   g_dp);
    cudaGetSymbolAddress((void**)&p_res,  g_res);

    dim3 blk8(32,8);

    // 1. layernorm -> xn[f,b,l,c]
    k_ln<<<dim3(128,2,2),256>>>(x1,x2,ln_g,ln_b);
    // 2. in_proj (NT): xz[fb][d2][l] = W(512x128) * xn[fb]^T
    gemm_nt64<<<dim3(64,8,4),256>>>(in_proj_w, p_xn, p_xz,
        512,4096,128, 0L,1,1, (long)LL*DM,1,4, (long)512*LL);
    // 3. direction remap
    k_remap<<<dim3(4,512,12),256>>>();
    // 4. causal conv + silu -> xcv_dm[z][d][t]
    k_conv<<<dim3(16,256,12),256>>>(conv_w, conv_b);
    // 5. xproj (NN, transposed out): dblT[z][r][t] = xpw(40x256) * xcv_dm[z]
    gemm_nn64<<<dim3(64,1,12),256>>>(xproj_w, p_dm, p_dblT,
        40,4096,256, 40L*DI,2,3, (long)DI*LL,1,12, 40L*LL);
    // 6. dt projection + softplus (coalesced)
    k_dtproj<<<dim3(16,256,12),256>>>(dtproj_w, dtproj_b);
    // 7. selective scan + gate
    k_scan<<<dim3(16,12),256>>>(A_log, Dvec);
    // 8. combine 3 directions
    k_combine<<<dim3(4,256,4),blk8>>>();
    // 9. out_proj (NN): feat[fb][c][l] = opw(128x256) * ycomb[fb]
    gemm_nn64<<<dim3(64,2,4),256>>>(out_proj_w, p_ycomb, p_feat,
        128,4096,256, 0L,1,1, (long)DI*LL,1,4, (long)DM*LL);
    // 10. dp split-K + deterministic reduce
    k_dp<<<dim3(2,2,32),256>>>(p_feat, p_dpp);
    k_dpred<<<128,256>>>();
    // 11. res (NN): res[b][c][l] = dp[b](128x128) * Bf[b]
    gemm_nn64<<<dim3(64,2,2),256>>>(p_dp, p_feat + 2L*DM*LL, p_res,
        128,4096,128, (long)DM*DM,1,2, (long)DM*LL,1,2, (long)DM*LL);
    // 12. remap res -> out layout (b, c', h, w) == flat (l*128 + c)
    k_resremap<<<dim3(128,4,2),blk8>>>(outp);
    // 13-14. batchnorm over (b,h,w)
    k_bnstats<<<128,256>>>(outp);
    k_bnapply<<<4096,256>>>(outp, bn_g, bn_b);
}

// round 10
// speedup vs baseline: 1.6640x; 1.0856x over previous
#include <cuda_runtime.h>
#include <math.h>

#define LL 4096
#define DM 128
#define DI 256
#define DS 16
#define EPS 1e-5f

// ---------------- scratch (static device allocations; allowed) ----------------
__device__ float g_xn   [2*2*LL*DM];     // [f][b][l][c]
__device__ float g_xz   [4*512*LL];      // [f*2+b][d2][l]
__device__ float g_xzd  [12*512*LL];     // [(f*3+dir)*2+b][d2][t]  (dirs 1,2 only)
__device__ float g_xcv_dm[12*DI*LL];     // [z][d][t]
__device__ float g_dblT [12*40*LL];      // [z][r][t]
__device__ float g_dt   [12*DI*LL];      // [z][d][t]
__device__ float g_ydir [12*DI*LL];      // [z][d][t]
__device__ float g_ycomb[4*DI*LL];       // [f*2+b][d][l]
__device__ float g_feat [4*DM*LL];       // [f*2+b][c][l]
__device__ float g_dpp  [32*DM*DM];      // split-K partials for dp
__device__ float g_dp   [2*DM*DM];
__device__ float g_res  [2*DM*LL];
__device__ float g_bnmu [DM];
__device__ float g_bnrv [DM];

// base of the direction-ordered xz stream for batch-z (dir0 aliases g_xz)
__device__ __forceinline__ const float* xz_base(int z){
    int dir = (z%6)>>1;
    if (dir==0){ int fb = (z/6)*2 + (z&1); return g_xz + (long)fb*512*LL; }
    return g_xzd + (long)z*512*LL;
}

// ---------------- layernorm over channels: x[b,c,l] -> xn[f,b,l,c] ------------
__global__ void k_ln(const float* __restrict__ x1, const float* __restrict__ x2,
                     const float* __restrict__ lg, const float* __restrict__ lb)
{
    __shared__ float s[DM][33];
    __shared__ float mu_s[32], rv_s[32];
    int f = blockIdx.z, b = blockIdx.y, l0 = blockIdx.x*32, tid = threadIdx.x;
    const float* x = (f==0 ? x1 : x2) + (long)b*DM*LL;
    for (int idx=tid; idx<DM*32; idx+=256){
        int c = idx>>5, li = idx&31;
        s[c][li] = x[(long)c*LL + l0+li];
    }
    __syncthreads();
    if (tid < 32){
        float sum=0.f, sq=0.f;
        #pragma unroll 8
        for (int c=0;c<DM;c++){ float v=s[c][tid]; sum+=v; sq+=v*v; }
        float mu = sum*(1.f/DM);
        float var = sq*(1.f/DM) - mu*mu;
        mu_s[tid]=mu; rv_s[tid]=rsqrtf(var+EPS);
    }
    __syncthreads();
    float* outp = g_xn + ((long)(f*2+b)*LL + l0)*DM;
    for (int idx=tid; idx<32*DM; idx+=256){
        int li = idx>>7, c = idx&127;
        outp[(long)li*DM + c] = (s[c][li]-mu_s[li])*rv_s[li]*lg[c] + lb[c];
    }
}

// ======== 64(M)x128(N)-tile SGEMM, 256 threads, 4x8 outputs/thread ============
// NT: C[M,N] = A[M,K] * B[N,K]^T
__global__ void gemm_nt128(const float* __restrict__ A, const float* __restrict__ B,
                           float* __restrict__ C, int M,int N,int K,
                           int lda,int ldb,int ldc,
                           long aS,int aDiv,int aMod, long bS,int bDiv,int bMod, long cS)
{
    int z = blockIdx.z;
    A += (long)((z/aDiv)%aMod)*aS;
    B += (long)((z/bDiv)%bMod)*bS;
    C += (long)z*cS;
    int tid = threadIdx.x;
    int m0 = blockIdx.y*64, n0 = blockIdx.x*128;
    int lr = tid>>2, lk4 = (tid&3)*4;
    int ty = tid>>4, tx = tid&15;
    __shared__ float As[16][68], Bs[16][132];
    float acc[4][8] = {};
    bool am = (m0+lr) < M;
    for (int k0=0;k0<K;k0+=16){
        float4 av = am ? *(const float4*)(A + (long)(m0+lr)*lda + k0+lk4)
                       : make_float4(0.f,0.f,0.f,0.f);
        float4 b0 = *(const float4*)(B + (long)(n0+lr)*ldb + k0+lk4);
        float4 b1 = *(const float4*)(B + (long)(n0+64+lr)*ldb + k0+lk4);
        As[lk4+0][lr]=av.x; As[lk4+1][lr]=av.y; As[lk4+2][lr]=av.z; As[lk4+3][lr]=av.w;
        Bs[lk4+0][lr]=b0.x; Bs[lk4+1][lr]=b0.y; Bs[lk4+2][lr]=b0.z; Bs[lk4+3][lr]=b0.w;
        Bs[lk4+0][64+lr]=b1.x; Bs[lk4+1][64+lr]=b1.y; Bs[lk4+2][64+lr]=b1.z; Bs[lk4+3][64+lr]=b1.w;
        __syncthreads();
        #pragma unroll
        for (int kk=0;kk<16;kk++){
            float4 a  = *(const float4*)&As[kk][ty*4];
            float4 v0 = *(const float4*)&Bs[kk][tx*4];
            float4 v1 = *(const float4*)&Bs[kk][64+tx*4];
            float aa[4]={a.x,a.y,a.z,a.w};
            float bb[8]={v0.x,v0.y,v0.z,v0.w,v1.x,v1.y,v1.z,v1.w};
            #pragma unroll
            for (int i=0;i<4;i++)
                #pragma unroll
                for (int j=0;j<8;j++) acc[i][j] += aa[i]*bb[j];
        }
        __syncthreads();
    }
    #pragma unroll
    for (int i=0;i<4;i++){
        int m = m0+ty*4+i;
        if (m < M){
            float4 o0 = make_float4(acc[i][0],acc[i][1],acc[i][2],acc[i][3]);
            float4 o1 = make_float4(acc[i][4],acc[i][5],acc[i][6],acc[i][7]);
            *(float4*)(C + (long)m*ldc + n0+tx*4)    = o0;
            *(float4*)(C + (long)m*ldc + n0+64+tx*4) = o1;
        }
    }
}

// NN: C[M,N] = A[M,K] * B[K,N]
__global__ void gemm_nn128(const float* __restrict__ A, const float* __restrict__ B,
                           float* __restrict__ C, int M,int N,int K,
                           int lda,int ldb,int ldc,
                           long aS,int aDiv,int aMod, long bS,int bDiv,int bMod, long cS)
{
    int z = blockIdx.z;
    A += (long)((z/aDiv)%aMod)*aS;
    B += (long)((z/bDiv)%bMod)*bS;
    C += (long)z*cS;
    int tid = threadIdx.x;
    int m0 = blockIdx.y*64, n0 = blockIdx.x*128;
    int lr = tid>>2, lk4 = (tid&3)*4;
    int bk = tid>>5, bn4 = (tid&31)*4;
    int ty = tid>>4, tx = tid&15;
    __shared__ float As[16][68], Bs[16][132];
    float acc[4][8] = {};
    bool am = (m0+lr) < M;
    for (int k0=0;k0<K;k0+=16){
        float4 av = am ? *(const float4*)(A + (long)(m0+lr)*lda + k0+lk4)
                       : make_float4(0.f,0.f,0.f,0.f);
        As[lk4+0][lr]=av.x; As[lk4+1][lr]=av.y; As[lk4+2][lr]=av.z; As[lk4+3][lr]=av.w;
        *(float4*)&Bs[bk][bn4]   = *(const float4*)(B + (long)(k0+bk)*ldb   + n0+bn4);
        *(float4*)&Bs[bk+8][bn4] = *(const float4*)(B + (long)(k0+bk+8)*ldb + n0+bn4);
        __syncthreads();
        #pragma unroll
        for (int kk=0;kk<16;kk++){
            float4 a  = *(const float4*)&As[kk][ty*4];
            float4 v0 = *(const float4*)&Bs[kk][tx*4];
            float4 v1 = *(const float4*)&Bs[kk][64+tx*4];
            float aa[4]={a.x,a.y,a.z,a.w};
            float bb[8]={v0.x,v0.y,v0.z,v0.w,v1.x,v1.y,v1.z,v1.w};
            #pragma unroll
            for (int i=0;i<4;i++)
                #pragma unroll
                for (int j=0;j<8;j++) acc[i][j] += aa[i]*bb[j];
        }
        __syncthreads();
    }
    #pragma unroll
    for (int i=0;i<4;i++){
        int m = m0+ty*4+i;
        if (m < M){
            float4 o0 = make_float4(acc[i][0],acc[i][1],acc[i][2],acc[i][3]);
            float4 o1 = make_float4(acc[i][4],acc[i][5],acc[i][6],acc[i][7]);
            *(float4*)(C + (long)m*ldc + n0+tx*4)    = o0;
            *(float4*)(C + (long)m*ldc + n0+64+tx*4) = o1;
        }
    }
}

// ---------------- split-K dp: dpp[b*16+ch][c][d] = A_chunk * Bf_chunk^T -------
__global__ void k_dp(const float* __restrict__ feat, float* __restrict__ dpp)
{
    int zz = blockIdx.z; int b = zz>>4, ch = zz&15;
    const float* A  = feat + (long)b    *DM*LL + ch*256;
    const float* Bp = feat + (long)(2+b)*DM*LL + ch*256;
    int tid = threadIdx.x;
    int tx = tid&15, ty = tid>>4;
    int n0 = blockIdx.x*64, m0 = blockIdx.y*64;
    int lm = tid>>2, lk4 = (tid&3)*4;
    __shared__ float As[16][68], Bs[16][68];
    float acc[4][4] = {};
    for (int k0=0;k0<256;k0+=16){
        float4 av = *(const float4*)(A  + (long)(m0+lm)*LL + k0+lk4);
        float4 bv = *(const float4*)(Bp + (long)(n0+lm)*LL + k0+lk4);
        As[lk4+0][lm]=av.x; As[lk4+1][lm]=av.y; As[lk4+2][lm]=av.z; As[lk4+3][lm]=av.w;
        Bs[lk4+0][lm]=bv.x; Bs[lk4+1][lm]=bv.y; Bs[lk4+2][lm]=bv.z; Bs[lk4+3][lm]=bv.w;
        __syncthreads();
        #pragma unroll
        for (int kk=0;kk<16;kk++){
            float4 a = *(const float4*)&As[kk][ty*4];
            float4 b = *(const float4*)&Bs[kk][tx*4];
            float aa[4]={a.x,a.y,a.z,a.w}, bb[4]={b.x,b.y,b.z,b.w};
            #pragma unroll
            for (int i=0;i<4;i++)
                #pragma unroll
                for (int j=0;j<4;j++) acc[i][j] += aa[i]*bb[j];
        }
        __syncthreads();
    }
    float* Cp = dpp + (long)zz*DM*DM;
    #pragma unroll
    for (int i=0;i<4;i++)
        #pragma unroll
        for (int j=0;j<4;j++)
            Cp[(long)(m0+ty*4+i)*DM + n0+tx*4+j] = acc[i][j];
}

__global__ void k_dpred()
{
    int i = blockIdx.x*256 + threadIdx.x;   // 0..32767
    int b = i>>14, j = i&16383;
    float s = 0.f;
    #pragma unroll
    for (int ch=0;ch<16;ch++) s += g_dpp[(long)(b*16+ch)*DM*DM + j];
    g_dp[(long)b*DM*DM + j] = s;
}

// ---------------- direction remap: xz -> xzd (flip / 64x64 T); dirs 1,2 only --
__global__ void k_remap()
{
    int zr = blockIdx.z;
    int f = zr>>2, dirm = (zr>>1)&1, b = zr&1;
    int dir = 1+dirm;
    int z = (f*3+dir)*2+b;
    int fb = f*2+b;
    const float* src = g_xz  + (long)fb*512*LL;
    float*       dst = g_xzd + (long)z *512*LL;
    int d = blockIdx.y, tid = threadIdx.x;
    __shared__ float s[32][33];
    if (dir==1){
        int t = blockIdx.x*1024 + tid*4;
        const float* sr = src + (long)d*LL;
        float*       dw = dst + (long)d*LL;
        #pragma unroll
        for (int j=0;j<4;j++) dw[t+j] = sr[LL-1-(t+j)];
    } else {
        int a0 = (blockIdx.x&1)*32, b0 = (blockIdx.x>>1)*32;
        const float* sr = src + (long)d*LL;
        float*       dw = dst + (long)d*LL;
        #pragma unroll
        for (int q=0;q<4;q++){
            int idx = tid + q*256;
            int bb = idx>>5, aa = idx&31;
            s[bb][aa] = sr[(b0+bb)*64 + a0+aa];
        }
        __syncthreads();
        #pragma unroll
        for (int q=0;q<4;q++){
            int idx = tid + q*256;
            int aa = idx>>5, bb = idx&31;
            dw[(a0+aa)*64 + b0+bb] = s[bb][aa];
        }
    }
}

// ---------------- causal depthwise conv (DC=4) + silu, 4 t/thread -------------
__global__ void k_conv(const float* __restrict__ cw, const float* __restrict__ cb)
{
    int z = blockIdx.z;
    int dir = (z%6)>>1;
    int d = blockIdx.y;
    int t0 = (blockIdx.x*256 + threadIdx.x)*4;
    const float* row = xz_base(z) + (long)d*LL;
    float4 cur = *(const float4*)(row + t0);
    float p1,p2,p3;
    if (t0 >= 4){
        float4 pv = *(const float4*)(row + t0 - 4);
        p1=pv.y; p2=pv.z; p3=pv.w;
    } else { p1=p2=p3=0.f; }
    float xs[7] = {p1,p2,p3,cur.x,cur.y,cur.z,cur.w};
    float4 wv = *(const float4*)(cw + (long)(dir*DI + d)*4);
    float bias = cb[dir*DI + d];
    float out[4];
    #pragma unroll
    for (int j=0;j<4;j++){
        float a = bias + wv.x*xs[j] + wv.y*xs[j+1] + wv.z*xs[j+2] + wv.w*xs[j+3];
        out[j] = a / (1.f + __expf(-a));
    }
    *(float4*)(g_xcv_dm + (long)z*DI*LL + (long)d*LL + t0) =
        make_float4(out[0],out[1],out[2],out[3]);
}

// ---------------- dt = softplus(dpw @ dblT[:8] + dpb), smem-staged ------------
__global__ void k_dtproj(const float* __restrict__ dpw, const float* __restrict__ dpb)
{
    int z = blockIdx.z;
    int dir = (z%6)>>1;
    int t0 = blockIdx.x*256, d0 = blockIdx.y*64;
    int tid = threadIdx.x;
    __shared__ float sB[8][260];
    __shared__ float sWf[512];
    __shared__ float sBias[64];
    {   // stage B rows (8 x 256)
        int r = tid>>5, c = tid&31;
        const float* src = g_dblT + (long)z*40*LL + (long)r*LL + t0;
        *(float4*)&sB[r][c*4]     = *(const float4*)(src + c*4);
        *(float4*)&sB[r][128+c*4] = *(const float4*)(src + 128 + c*4);
    }
    if (tid < 128)
        *(float4*)&sWf[tid*4] = *(const float4*)(dpw + (long)(dir*DI + d0)*8 + tid*4);
    if (tid < 64)
        sBias[tid] = dpb[dir*DI + d0 + tid];
    __syncthreads();
    int dgrp = tid>>4, tg = tid&15;
    float w[4][8], bs[4];
    #pragma unroll
    for (int i=0;i<4;i++){
        bs[i] = sBias[dgrp*4+i];
        #pragma unroll
        for (int r=0;r<8;r++) w[i][r] = sWf[(dgrp*4+i)*8 + r];
    }
    float* dst = g_dt + (long)z*DI*LL;
    #pragma unroll 4
    for (int jj=0;jj<16;jj++){
        int tl = tg + 16*jj;
        float xv[8];
        #pragma unroll
        for (int r=0;r<8;r++) xv[r] = sB[r][tl];
        #pragma unroll
        for (int i=0;i<4;i++){
            float a = bs[i];
            #pragma unroll
            for (int r=0;r<8;r++) a += w[i][r]*xv[r];
            float sp = fmaxf(a,0.f) + log1pf(__expf(-fabsf(a)));
            dst[(long)(d0+dgrp*4+i)*LL + t0+tl] = sp;
        }
    }
}

// ---------------- selective scan: 16 lanes per (b,d), shfl-reduce y -----------
__global__ void k_scan(const float* __restrict__ A_log, const float* __restrict__ Dp)
{
    int z = blockIdx.y;
    int dir = (z%6)>>1;
    int d0 = blockIdx.x*16;
    int tid = threadIdx.x;
    int warp = tid>>5, lane = tid&31;
    int g = warp*2 + (lane>>4);
    int n = lane&15;
    int d = d0+g;
    float An = -__expf(A_log[(long)(dir*DI + d)*DS + n]);

    const float* dtB  = g_dt     + (long)z*DI*LL;
    const float* xB   = g_xcv_dm + (long)z*DI*LL;
    const float* dblT = g_dblT   + (long)z*40*LL;
    const float* zB   = xz_base(z) + (long)DI*LL;
    float* yB = g_ydir + (long)z*DI*LL;

    __shared__ float s_dt[16][129], s_x[16][129], s_y[16][129];
    __shared__ float s_Bc[128][17], s_Cc[128][17];
    float h = 0.f;

    for (int c0=0;c0<LL;c0+=128){
        for (int idx=tid; idx<16*128; idx+=256){
            int r = idx>>7, cc = idx&127;
            s_dt[r][cc] = dtB[(long)(d0+r)*LL + c0+cc];
            s_x[r][cc]  = xB [(long)(d0+r)*LL + c0+cc];
        }
        for (int idx=tid; idx<16*128; idx+=256){
            int nn = idx>>7, tt = idx&127;
            s_Bc[tt][nn] = dblT[(long)(8+nn)*LL + c0+tt];
            s_Cc[tt][nn] = dblT[(long)(24+nn)*LL + c0+tt];
        }
        __syncthreads();
        #pragma unroll 4
        for (int t=0;t<128;t++){
            float dtv = s_dt[g][t];
            float xv  = s_x [g][t];
            float da = __expf(dtv*An);
            h = da*h + (dtv*xv)*s_Bc[t][n];
            float p = h*s_Cc[t][n];
            p += __shfl_xor_sync(0xffffffffu, p, 8);
            p += __shfl_xor_sync(0xffffffffu, p, 4);
            p += __shfl_xor_sync(0xffffffffu, p, 2);
            p += __shfl_xor_sync(0xffffffffu, p, 1);
            if (n==0) s_y[g][t] = p;
        }
        __syncthreads();
        for (int idx=tid; idx<16*128; idx+=256){
            int r = idx>>7, cc = idx&127;
            int dd = d0+r; int tt = c0+cc;
            float zv = zB[(long)dd*LL + tt];
            float sz = zv / (1.f + __expf(-zv));
            yB[(long)dd*LL + tt] = (s_y[r][cc] + Dp[dir*DI+dd]*s_x[r][cc]) * sz;
        }
        __syncthreads();
    }
}

// ---------------- combine 3 directions (fwd + flip + 64x64 transpose) ---------
__global__ void k_combine()
{
    int z2 = blockIdx.z, d = blockIdx.y;
    int f = z2>>1, b = z2&1;
    long off0 = ((long)((f*3+0)*2+b)*DI + d)*LL;
    long off1 = ((long)((f*3+1)*2+b)*DI + d)*LL;
    long off2 = ((long)((f*3+2)*2+b)*DI + d)*LL;
    long offo = ((long)z2*DI + d)*LL;
    int i0 = (blockIdx.x&1)*32, j0 = (blockIdx.x>>1)*32;
    int tx=threadIdx.x, ty=threadIdx.y;
    __shared__ float s[32][33];
    #pragma unroll
    for (int r=0;r<4;r++){
        int jj = ty+8*r;
        s[jj][tx] = g_ydir[off2 + (j0+jj)*64 + i0+tx];
    }
    __syncthreads();
    #pragma unroll
    for (int r=0;r<4;r++){
        int ii = ty+8*r;
        int l = (i0+ii)*64 + j0+tx;
        g_ycomb[offo + l] = g_ydir[off0 + l] + g_ydir[off1 + (LL-1-l)] + s[tx][ii];
    }
}

// ---------------- res[c][l] -> out flat (l*128 + c), via tile transpose -------
__global__ void k_resremap(float* __restrict__ outp)
{
    int b = blockIdx.z, c0 = blockIdx.y*32, l0 = blockIdx.x*32;
    int tx=threadIdx.x, ty=threadIdx.y;
    __shared__ float s[32][33];
    #pragma unroll
    for (int r=0;r<4;r++){
        int cl = ty+8*r;
        s[cl][tx] = g_res[(long)b*DM*LL + (long)(c0+cl)*LL + l0+tx];
    }
    __syncthreads();
    #pragma unroll
    for (int r=0;r<4;r++){
        int ll = ty+8*r;
        outp[(long)b*DM*LL + (long)(l0+ll)*DM + c0+tx] = s[tx][ll];
    }
}

// ---------------- batchnorm over (b,h,w) per channel --------------------------
__global__ void k_bnstats(const float* __restrict__ outp)
{
    int cc = blockIdx.x, tid = threadIdx.x;
    __shared__ float ss[256], sq[256];
    float a=0.f, q=0.f;
    for (int i=tid;i<2*LL;i+=256){
        float v = outp[(long)(i>>12)*DM*LL + (long)cc*LL + (i&(LL-1))];
        a+=v; q+=v*v;
    }
    ss[tid]=a; sq[tid]=q;
    __syncthreads();
    for (int st=128; st>0; st>>=1){
        if (tid<st){ ss[tid]+=ss[tid+st]; sq[tid]+=sq[tid+st]; }
        __syncthreads();
    }
    if (tid==0){
        float mu = ss[0]*(1.f/(2*LL));
        float var = sq[0]*(1.f/(2*LL)) - mu*mu;
        g_bnmu[cc]=mu; g_bnrv[cc]=rsqrtf(var+EPS);
    }
}

__global__ void k_bnapply(float* __restrict__ outp, const float* __restrict__ bg,
                          const float* __restrict__ bb)
{
    long gi = (long)blockIdx.x*256 + threadIdx.x;
    int cc = (int)((gi>>12)&127);
    outp[gi] = (outp[gi]-g_bnmu[cc])*g_bnrv[cc]*bg[cc] + bb[cc];
}

// ---------------- launcher ----------------------------------------------------
extern "C" void kernel_launch(void* const* d_in, const int* in_sizes, int n_in,
                              void* d_out, int out_size)
{
    const float* x1        = (const float*)d_in[0];
    const float* x2        = (const float*)d_in[1];
    const float* ln_g      = (const float*)d_in[2];
    const float* ln_b      = (const float*)d_in[3];
    const float* in_proj_w = (const float*)d_in[4];
    const float* conv_w    = (const float*)d_in[5];
    const float* conv_b    = (const float*)d_in[6];
    const float* xproj_w   = (const float*)d_in[7];
    const float* dtproj_w  = (const float*)d_in[8];
    const float* dtproj_b  = (const float*)d_in[9];
    const float* A_log     = (const float*)d_in[10];
    const float* Dvec      = (const float*)d_in[11];
    const float* out_proj_w= (const float*)d_in[12];
    const float* bn_g      = (const float*)d_in[13];
    const float* bn_b      = (const float*)d_in[14];
    float* outp = (float*)d_out;

    float *p_xn,*p_xz,*p_dm,*p_dblT,*p_ycomb,*p_feat,*p_dpp,*p_dp,*p_res;
    cudaGetSymbolAddress((void**)&p_xn,   g_xn);
    cudaGetSymbolAddress((void**)&p_xz,   g_xz);
    cudaGetSymbolAddress((void**)&p_dm,   g_xcv_dm);
    cudaGetSymbolAddress((void**)&p_dblT, g_dblT);
    cudaGetSymbolAddress((void**)&p_ycomb,g_ycomb);
    cudaGetSymbolAddress((void**)&p_feat, g_feat);
    cudaGetSymbolAddress((void**)&p_dpp,  g_dpp);
    cudaGetSymbolAddress((void**)&p_dp,   g_dp);
    cudaGetSymbolAddress((void**)&p_res,  g_res);

    dim3 blk8(32,8);

    // 1. layernorm -> xn[f,b,l,c]
    k_ln<<<dim3(128,2,2),256>>>(x1,x2,ln_g,ln_b);
    // 2. in_proj (NT): xz[fb][d2][l] = W(512x128) * xn[fb]^T
    gemm_nt128<<<dim3(32,8,4),256>>>(in_proj_w, p_xn, p_xz,
        512,4096,128, 128,128,4096,
        0L,1,1, (long)LL*DM,1,4, (long)512*LL);
    // 3. direction remap (dirs 1,2 only)
    k_remap<<<dim3(4,512,8),256>>>();
    // 4. causal conv + silu -> xcv_dm[z][d][t]
    k_conv<<<dim3(4,256,12),256>>>(conv_w, conv_b);
    // 5. xproj (NN): dblT[z][r][t] = xpw(40x256) * xcv_dm[z](256x4096)
    gemm_nn128<<<dim3(32,1,12),256>>>(xproj_w, p_dm, p_dblT,
        40,4096,256, 256,4096,4096,
        40L*DI,2,3, (long)DI*LL,1,12, 40L*LL);
    // 6. dt projection + softplus (smem-staged)
    k_dtproj<<<dim3(16,4,12),256>>>(dtproj_w, dtproj_b);
    // 7. selective scan + gate
    k_scan<<<dim3(16,12),256>>>(A_log, Dvec);
    // 8. combine 3 directions
    k_combine<<<dim3(4,256,4),blk8>>>();
    // 9. out_proj (NN): feat[fb][c][l] = opw(128x256) * ycomb[fb]
    gemm_nn128<<<dim3(32,2,4),256>>>(out_proj_w, p_ycomb, p_feat,
        128,4096,256, 256,4096,4096,
        0L,1,1, (long)DI*LL,1,4, (long)DM*LL);
    // 10. dp split-K + deterministic reduce
    k_dp<<<dim3(2,2,32),256>>>(p_feat, p_dpp);
    k_dpred<<<128,256>>>();
    // 11. res (NN): res[b][c][l] = dp[b](128x128) * Bf[b]
    gemm_nn128<<<dim3(32,2,2),256>>>(p_dp, p_feat + 2L*DM*LL, p_res,
        128,4096,128, 128,4096,4096,
        (long)DM*DM,1,2, (long)DM*LL,1,2, (long)DM*LL);
    // 12. remap res -> out layout (b, c', h, w) == flat (l*128 + c)
    k_resremap<<<dim3(128,4,2),blk8>>>(outp);
    // 13-14. batchnorm over (b,h,w)
    k_bnstats<<<128,256>>>(outp);
    k_bnapply<<<4096,256>>>(outp, bn_g, bn_b);
}

// round 13
// speedup vs baseline: 2.5636x; 1.5406x over previous
#include <cuda_runtime.h>
#include <math.h>

#define LL 4096
#define DM 128
#define DI 256
#define DS 16
#define NCH 32
#define CHL 128
#define EPS 1e-5f

// ---------------- scratch (static device allocations; allowed) ----------------
__device__ float g_xn   [2*2*LL*DM];     // [f][b][l][c]
__device__ float g_xz   [4*512*LL];      // [f*2+b][d2][l]
__device__ float g_xzd  [12*512*LL];     // [(f*3+dir)*2+b][d2][t]  (dirs 1,2 only)
__device__ float g_xcv_dm[12*DI*LL];     // [z][d][t]
__device__ float g_dblT [12*40*LL];      // [z][r][t]
__device__ float g_dt   [12*DI*LL];      // [z][d][t]
__device__ float g_ydir [12*DI*LL];      // [z][d][t]
__device__ float g_ycomb[4*DI*LL];       // [f*2+b][d][l]
__device__ float g_feat [4*DM*LL];       // [f*2+b][c][l]
__device__ float g_dpp  [32*DM*DM];      // split-K partials for dp
__device__ float g_dp   [2*DM*DM];
__device__ float g_res  [2*DM*LL];
__device__ float g_bnmu [DM];
__device__ float g_bnrv [DM];
// chunked-scan state
__device__ float g_hloc [12*NCH*DI*DS];  // chunk-local h_out
__device__ float g_hin  [12*NCH*DI*DS];  // composed h at chunk entry
__device__ float g_sdt  [12*NCH*DI];     // sum of dt per chunk per d

// base of the direction-ordered xz stream for batch-z (dir0 aliases g_xz)
__device__ __forceinline__ const float* xz_base(int z){
    int dir = (z%6)>>1;
    if (dir==0){ int fb = (z/6)*2 + (z&1); return g_xz + (long)fb*512*LL; }
    return g_xzd + (long)z*512*LL;
}

// ---------------- layernorm over channels: x[b,c,l] -> xn[f,b,l,c] ------------
__global__ void k_ln(const float* __restrict__ x1, const float* __restrict__ x2,
                     const float* __restrict__ lg, const float* __restrict__ lb)
{
    __shared__ float s[DM][33];
    __shared__ float mu_s[32], rv_s[32];
    int f = blockIdx.z, b = blockIdx.y, l0 = blockIdx.x*32, tid = threadIdx.x;
    const float* x = (f==0 ? x1 : x2) + (long)b*DM*LL;
    for (int idx=tid; idx<DM*32; idx+=256){
        int c = idx>>5, li = idx&31;
        s[c][li] = x[(long)c*LL + l0+li];
    }
    __syncthreads();
    if (tid < 32){
        float sum=0.f, sq=0.f;
        #pragma unroll 8
        for (int c=0;c<DM;c++){ float v=s[c][tid]; sum+=v; sq+=v*v; }
        float mu = sum*(1.f/DM);
        float var = sq*(1.f/DM) - mu*mu;
        mu_s[tid]=mu; rv_s[tid]=rsqrtf(var+EPS);
    }
    __syncthreads();
    float* outp = g_xn + ((long)(f*2+b)*LL + l0)*DM;
    for (int idx=tid; idx<32*DM; idx+=256){
        int li = idx>>7, c = idx&127;
        outp[(long)li*DM + c] = (s[c][li]-mu_s[li])*rv_s[li]*lg[c] + lb[c];
    }
}

// ======== 64(M)x128(N)-tile SGEMM, 256 threads, 4x8 outputs/thread ============
// NT: C[M,N] = A[M,K] * B[N,K]^T
__global__ void gemm_nt128(const float* __restrict__ A, const float* __restrict__ B,
                           float* __restrict__ C, int M,int N,int K,
                           int lda,int ldb,int ldc,
                           long aS,int aDiv,int aMod, long bS,int bDiv,int bMod, long cS)
{
    int z = blockIdx.z;
    A += (long)((z/aDiv)%aMod)*aS;
    B += (long)((z/bDiv)%bMod)*bS;
    C += (long)z*cS;
    int tid = threadIdx.x;
    int m0 = blockIdx.y*64, n0 = blockIdx.x*128;
    int lr = tid>>2, lk4 = (tid&3)*4;
    int ty = tid>>4, tx = tid&15;
    __shared__ float As[16][68], Bs[16][132];
    float acc[4][8] = {};
    bool am = (m0+lr) < M;
    for (int k0=0;k0<K;k0+=16){
        float4 av = am ? *(const float4*)(A + (long)(m0+lr)*lda + k0+lk4)
                       : make_float4(0.f,0.f,0.f,0.f);
        float4 b0 = *(const float4*)(B + (long)(n0+lr)*ldb + k0+lk4);
        float4 b1 = *(const float4*)(B + (long)(n0+64+lr)*ldb + k0+lk4);
        As[lk4+0][lr]=av.x; As[lk4+1][lr]=av.y; As[lk4+2][lr]=av.z; As[lk4+3][lr]=av.w;
        Bs[lk4+0][lr]=b0.x; Bs[lk4+1][lr]=b0.y; Bs[lk4+2][lr]=b0.z; Bs[lk4+3][lr]=b0.w;
        Bs[lk4+0][64+lr]=b1.x; Bs[lk4+1][64+lr]=b1.y; Bs[lk4+2][64+lr]=b1.z; Bs[lk4+3][64+lr]=b1.w;
        __syncthreads();
        #pragma unroll
        for (int kk=0;kk<16;kk++){
            float4 a  = *(const float4*)&As[kk][ty*4];
            float4 v0 = *(const float4*)&Bs[kk][tx*4];
            float4 v1 = *(const float4*)&Bs[kk][64+tx*4];
            float aa[4]={a.x,a.y,a.z,a.w};
            float bb[8]={v0.x,v0.y,v0.z,v0.w,v1.x,v1.y,v1.z,v1.w};
            #pragma unroll
            for (int i=0;i<4;i++)
                #pragma unroll
                for (int j=0;j<8;j++) acc[i][j] += aa[i]*bb[j];
        }
        __syncthreads();
    }
    #pragma unroll
    for (int i=0;i<4;i++){
        int m = m0+ty*4+i;
        if (m < M){
            float4 o0 = make_float4(acc[i][0],acc[i][1],acc[i][2],acc[i][3]);
            float4 o1 = make_float4(acc[i][4],acc[i][5],acc[i][6],acc[i][7]);
            *(float4*)(C + (long)m*ldc + n0+tx*4)    = o0;
            *(float4*)(C + (long)m*ldc + n0+64+tx*4) = o1;
        }
    }
}

// NN: C[M,N] = A[M,K] * B[K,N]
__global__ void gemm_nn128(const float* __restrict__ A, const float* __restrict__ B,
                           float* __restrict__ C, int M,int N,int K,
                           int lda,int ldb,int ldc,
                           long aS,int aDiv,int aMod, long bS,int bDiv,int bMod, long cS)
{
    int z = blockIdx.z;
    A += (long)((z/aDiv)%aMod)*aS;
    B += (long)((z/bDiv)%bMod)*bS;
    C += (long)z*cS;
    int tid = threadIdx.x;
    int m0 = blockIdx.y*64, n0 = blockIdx.x*128;
    int lr = tid>>2, lk4 = (tid&3)*4;
    int bk = tid>>5, bn4 = (tid&31)*4;
    int ty = tid>>4, tx = tid&15;
    __shared__ float As[16][68], Bs[16][132];
    float acc[4][8] = {};
    bool am = (m0+lr) < M;
    for (int k0=0;k0<K;k0+=16){
        float4 av = am ? *(const float4*)(A + (long)(m0+lr)*lda + k0+lk4)
                       : make_float4(0.f,0.f,0.f,0.f);
        As[lk4+0][lr]=av.x; As[lk4+1][lr]=av.y; As[lk4+2][lr]=av.z; As[lk4+3][lr]=av.w;
        *(float4*)&Bs[bk][bn4]   = *(const float4*)(B + (long)(k0+bk)*ldb   + n0+bn4);
        *(float4*)&Bs[bk+8][bn4] = *(const float4*)(B + (long)(k0+bk+8)*ldb + n0+bn4);
        __syncthreads();
        #pragma unroll
        for (int kk=0;kk<16;kk++){
            float4 a  = *(const float4*)&As[kk][ty*4];
            float4 v0 = *(const float4*)&Bs[kk][tx*4];
            float4 v1 = *(const float4*)&Bs[kk][64+tx*4];
            float aa[4]={a.x,a.y,a.z,a.w};
            float bb[8]={v0.x,v0.y,v0.z,v0.w,v1.x,v1.y,v1.z,v1.w};
            #pragma unroll
            for (int i=0;i<4;i++)
                #pragma unroll
                for (int j=0;j<8;j++) acc[i][j] += aa[i]*bb[j];
        }
        __syncthreads();
    }
    #pragma unroll
    for (int i=0;i<4;i++){
        int m = m0+ty*4+i;
        if (m < M){
            float4 o0 = make_float4(acc[i][0],acc[i][1],acc[i][2],acc[i][3]);
            float4 o1 = make_float4(acc[i][4],acc[i][5],acc[i][6],acc[i][7]);
            *(float4*)(C + (long)m*ldc + n0+tx*4)    = o0;
            *(float4*)(C + (long)m*ldc + n0+64+tx*4) = o1;
        }
    }
}

// ---------------- split-K dp: dpp[b*16+ch][c][d] = A_chunk * Bf_chunk^T -------
__global__ void k_dp(const float* __restrict__ feat, float* __restrict__ dpp)
{
    int zz = blockIdx.z; int b = zz>>4, ch = zz&15;
    const float* A  = feat + (long)b    *DM*LL + ch*256;
    const float* Bp = feat + (long)(2+b)*DM*LL + ch*256;
    int tid = threadIdx.x;
    int tx = tid&15, ty = tid>>4;
    int n0 = blockIdx.x*64, m0 = blockIdx.y*64;
    int lm = tid>>2, lk4 = (tid&3)*4;
    __shared__ float As[16][68], Bs[16][68];
    float acc[4][4] = {};
    for (int k0=0;k0<256;k0+=16){
        float4 av = *(const float4*)(A  + (long)(m0+lm)*LL + k0+lk4);
        float4 bv = *(const float4*)(Bp + (long)(n0+lm)*LL + k0+lk4);
        As[lk4+0][lm]=av.x; As[lk4+1][lm]=av.y; As[lk4+2][lm]=av.z; As[lk4+3][lm]=av.w;
        Bs[lk4+0][lm]=bv.x; Bs[lk4+1][lm]=bv.y; Bs[lk4+2][lm]=bv.z; Bs[lk4+3][lm]=bv.w;
        __syncthreads();
        #pragma unroll
        for (int kk=0;kk<16;kk++){
            float4 a = *(const float4*)&As[kk][ty*4];
            float4 b = *(const float4*)&Bs[kk][tx*4];
            float aa[4]={a.x,a.y,a.z,a.w}, bb[4]={b.x,b.y,b.z,b.w};
            #pragma unroll
            for (int i=0;i<4;i++)
                #pragma unroll
                for (int j=0;j<4;j++) acc[i][j] += aa[i]*bb[j];
        }
        __syncthreads();
    }
    float* Cp = dpp + (long)zz*DM*DM;
    #pragma unroll
    for (int i=0;i<4;i++)
        #pragma unroll
        for (int j=0;j<4;j++)
            Cp[(long)(m0+ty*4+i)*DM + n0+tx*4+j] = acc[i][j];
}

__global__ void k_dpred()
{
    int i = blockIdx.x*256 + threadIdx.x;   // 0..32767
    int b = i>>14, j = i&16383;
    float s = 0.f;
    #pragma unroll
    for (int ch=0;ch<16;ch++) s += g_dpp[(long)(b*16+ch)*DM*DM + j];
    g_dp[(long)b*DM*DM + j] = s;
}

// ---------------- direction remap: xz -> xzd (flip / 64x64 T); dirs 1,2 only --
__global__ void k_remap()
{
    int zr = blockIdx.z;
    int f = zr>>2, dirm = (zr>>1)&1, b = zr&1;
    int dir = 1+dirm;
    int z = (f*3+dir)*2+b;
    int fb = f*2+b;
    const float* src = g_xz  + (long)fb*512*LL;
    float*       dst = g_xzd + (long)z *512*LL;
    int d = blockIdx.y, tid = threadIdx.x;
    __shared__ float s[32][33];
    if (dir==1){
        int t = blockIdx.x*1024 + tid*4;
        const float* sr = src + (long)d*LL;
        float*       dw = dst + (long)d*LL;
        #pragma unroll
        for (int j=0;j<4;j++) dw[t+j] = sr[LL-1-(t+j)];
    } else {
        int a0 = (blockIdx.x&1)*32, b0 = (blockIdx.x>>1)*32;
        const float* sr = src + (long)d*LL;
        float*       dw = dst + (long)d*LL;
        #pragma unroll
        for (int q=0;q<4;q++){
            int idx = tid + q*256;
            int bb = idx>>5, aa = idx&31;
            s[bb][aa] = sr[(b0+bb)*64 + a0+aa];
        }
        __syncthreads();
        #pragma unroll
        for (int q=0;q<4;q++){
            int idx = tid + q*256;
            int aa = idx>>5, bb = idx&31;
            dw[(a0+aa)*64 + b0+bb] = s[bb][aa];
        }
    }
}

// ---------------- causal depthwise conv (DC=4) + silu, 4 t/thread -------------
__global__ void k_conv(const float* __restrict__ cw, const float* __restrict__ cb)
{
    int z = blockIdx.z;
    int dir = (z%6)>>1;
    int d = blockIdx.y;
    int t0 = (blockIdx.x*256 + threadIdx.x)*4;
    const float* row = xz_base(z) + (long)d*LL;
    float4 cur = *(const float4*)(row + t0);
    float p1,p2,p3;
    if (t0 >= 4){
        float4 pv = *(const float4*)(row + t0 - 4);
        p1=pv.y; p2=pv.z; p3=pv.w;
    } else { p1=p2=p3=0.f; }
    float xs[7] = {p1,p2,p3,cur.x,cur.y,cur.z,cur.w};
    float4 wv = *(const float4*)(cw + (long)(dir*DI + d)*4);
    float bias = cb[dir*DI + d];
    float out[4];
    #pragma unroll
    for (int j=0;j<4;j++){
        float a = bias + wv.x*xs[j] + wv.y*xs[j+1] + wv.z*xs[j+2] + wv.w*xs[j+3];
        out[j] = a / (1.f + __expf(-a));
    }
    *(float4*)(g_xcv_dm + (long)z*DI*LL + (long)d*LL + t0) =
        make_float4(out[0],out[1],out[2],out[3]);
}

// ---------------- dt = softplus(dpw @ dblT[:8] + dpb), smem-staged ------------
__global__ void k_dtproj(const float* __restrict__ dpw, const float* __restrict__ dpb)
{
    int z = blockIdx.z;
    int dir = (z%6)>>1;
    int t0 = blockIdx.x*256, d0 = blockIdx.y*64;
    int tid = threadIdx.x;
    __shared__ float sB[8][260];
    __shared__ float sWf[512];
    __shared__ float sBias[64];
    {   // stage B rows (8 x 256)
        int r = tid>>5, c = tid&31;
        const float* src = g_dblT + (long)z*40*LL + (long)r*LL + t0;
        *(float4*)&sB[r][c*4]     = *(const float4*)(src + c*4);
        *(float4*)&sB[r][128+c*4] = *(const float4*)(src + 128 + c*4);
    }
    if (tid < 128)
        *(float4*)&sWf[tid*4] = *(const float4*)(dpw + (long)(dir*DI + d0)*8 + tid*4);
    if (tid < 64)
        sBias[tid] = dpb[dir*DI + d0 + tid];
    __syncthreads();
    int dgrp = tid>>4, tg = tid&15;
    float w[4][8], bs[4];
    #pragma unroll
    for (int i=0;i<4;i++){
        bs[i] = sBias[dgrp*4+i];
        #pragma unroll
        for (int r=0;r<8;r++) w[i][r] = sWf[(dgrp*4+i)*8 + r];
    }
    float* dst = g_dt + (long)z*DI*LL;
    #pragma unroll 4
    for (int jj=0;jj<16;jj++){
        int tl = tg + 16*jj;
        float xv[8];
        #pragma unroll
        for (int r=0;r<8;r++) xv[r] = sB[r][tl];
        #pragma unroll
        for (int i=0;i<4;i++){
            float a = bs[i];
            #pragma unroll
            for (int r=0;r<8;r++) a += w[i][r]*xv[r];
            float sp = fmaxf(a,0.f) + log1pf(__expf(-fabsf(a)));
            dst[(long)(d0+dgrp*4+i)*LL + t0+tl] = sp;
        }
    }
}

// ======================= chunked selective scan ==============================
// Phase A: per-chunk local scan from h=0 -> g_hloc, plus per-chunk sum(dt)
__global__ void k_scan1(const float* __restrict__ A_log)
{
    int z = blockIdx.z;
    int dir = (z%6)>>1;
    int d0 = blockIdx.y*16;
    int ch = blockIdx.x, c0 = ch*CHL;
    int tid = threadIdx.x;
    int warp = tid>>5, lane = tid&31;
    int g = warp*2 + (lane>>4);
    int n = lane&15;
    int d = d0+g;
    float An = -__expf(A_log[(long)(dir*DI + d)*DS + n]);

    const float* dtB  = g_dt     + (long)z*DI*LL;
    const float* xB   = g_xcv_dm + (long)z*DI*LL;
    const float* dblT = g_dblT   + (long)z*40*LL;

    __shared__ float s_dt[16][129], s_x[16][129];
    __shared__ float s_Bc[128][17];

    for (int idx=tid; idx<16*128; idx+=256){
        int r = idx>>7, cc = idx&127;
        s_dt[r][cc] = dtB[(long)(d0+r)*LL + c0+cc];
        s_x[r][cc]  = xB [(long)(d0+r)*LL + c0+cc];
    }
    for (int idx=tid; idx<16*128; idx+=256){
        int nn = idx>>7, tt = idx&127;
        s_Bc[tt][nn] = dblT[(long)(8+nn)*LL + c0+tt];
    }
    __syncthreads();

    // per-d sum of dt over the chunk (lane n sums 8, then reduce over 16 lanes)
    float part = 0.f;
    #pragma unroll
    for (int j=0;j<8;j++) part += s_dt[g][n*8+j];
    part += __shfl_xor_sync(0xffffffffu, part, 8);
    part += __shfl_xor_sync(0xffffffffu, part, 4);
    part += __shfl_xor_sync(0xffffffffu, part, 2);
    part += __shfl_xor_sync(0xffffffffu, part, 1);
    if (n==0) g_sdt[(long)(z*NCH+ch)*DI + d] = part;

    float h = 0.f;
    #pragma unroll 4
    for (int t=0;t<CHL;t++){
        float dtv = s_dt[g][t];
        float xv  = s_x [g][t];
        h = __expf(dtv*An)*h + (dtv*xv)*s_Bc[t][n];
    }
    g_hloc[((long)(z*NCH+ch)*DI + d)*DS + n] = h;
}

// Phase B: compose chunk states serially (32 steps per (z,d,n))
__global__ void k_scan2(const float* __restrict__ A_log)
{
    int i = blockIdx.x*256 + threadIdx.x;      // 0..49151
    int z = i>>12, rem = i&4095;
    int d = rem>>4, n = rem&15;
    int dir = (z%6)>>1;
    float An = -__expf(A_log[(long)(dir*DI + d)*DS + n]);
    float h = 0.f;
    #pragma unroll 4
    for (int c=0;c<NCH;c++){
        long base = (long)(z*NCH+c)*DI + d;
        g_hin[base*DS + n] = h;
        float S = g_sdt[base];
        h = __expf(An*S)*h + g_hloc[base*DS + n];
    }
}

// Phase C: per-chunk full scan with y, starting from composed h_in
__global__ void k_scan3(const float* __restrict__ A_log, const float* __restrict__ Dp)
{
    int z = blockIdx.z;
    int dir = (z%6)>>1;
    int d0 = blockIdx.y*16;
    int ch = blockIdx.x, c0 = ch*CHL;
    int tid = threadIdx.x;
    int warp = tid>>5, lane = tid&31;
    int g = warp*2 + (lane>>4);
    int n = lane&15;
    int d = d0+g;
    float An = -__expf(A_log[(long)(dir*DI + d)*DS + n]);

    const float* dtB  = g_dt     + (long)z*DI*LL;
    const float* xB   = g_xcv_dm + (long)z*DI*LL;
    const float* dblT = g_dblT   + (long)z*40*LL;
    const float* zB   = xz_base(z) + (long)DI*LL;
    float* yB = g_ydir + (long)z*DI*LL;

    __shared__ float s_dt[16][129], s_x[16][129], s_y[16][129];
    __shared__ float s_Bc[128][17], s_Cc[128][17];

    for (int idx=tid; idx<16*128; idx+=256){
        int r = idx>>7, cc = idx&127;
        s_dt[r][cc] = dtB[(long)(d0+r)*LL + c0+cc];
        s_x[r][cc]  = xB [(long)(d0+r)*LL + c0+cc];
    }
    for (int idx=tid; idx<16*128; idx+=256){
        int nn = idx>>7, tt = idx&127;
        s_Bc[tt][nn] = dblT[(long)(8+nn)*LL + c0+tt];
        s_Cc[tt][nn] = dblT[(long)(24+nn)*LL + c0+tt];
    }
    float h = g_hin[((long)(z*NCH+ch)*DI + d)*DS + n];
    __syncthreads();

    #pragma unroll 4
    for (int t=0;t<CHL;t++){
        float dtv = s_dt[g][t];
        float xv  = s_x [g][t];
        float da = __expf(dtv*An);
        h = da*h + (dtv*xv)*s_Bc[t][n];
        float p = h*s_Cc[t][n];
        p += __shfl_xor_sync(0xffffffffu, p, 8);
        p += __shfl_xor_sync(0xffffffffu, p, 4);
        p += __shfl_xor_sync(0xffffffffu, p, 2);
        p += __shfl_xor_sync(0xffffffffu, p, 1);
        if (n==0) s_y[g][t] = p;
    }
    __syncthreads();
    for (int idx=tid; idx<16*128; idx+=256){
        int r = idx>>7, cc = idx&127;
        int dd = d0+r; int tt = c0+cc;
        float zv = zB[(long)dd*LL + tt];
        float sz = zv / (1.f + __expf(-zv));
        yB[(long)dd*LL + tt] = (s_y[r][cc] + Dp[dir*DI+dd]*s_x[r][cc]) * sz;
    }
}

// ---------------- combine 3 directions (fwd + flip + 64x64 transpose) ---------
__global__ void k_combine()
{
    int z2 = blockIdx.z, d = blockIdx.y;
    int f = z2>>1, b = z2&1;
    long off0 = ((long)((f*3+0)*2+b)*DI + d)*LL;
    long off1 = ((long)((f*3+1)*2+b)*DI + d)*LL;
    long off2 = ((long)((f*3+2)*2+b)*DI + d)*LL;
    long offo = ((long)z2*DI + d)*LL;
    int i0 = (blockIdx.x&1)*32, j0 = (blockIdx.x>>1)*32;
    int tx=threadIdx.x, ty=threadIdx.y;
    __shared__ float s[32][33];
    #pragma unroll
    for (int r=0;r<4;r++){
        int jj = ty+8*r;
        s[jj][tx] = g_ydir[off2 + (j0+jj)*64 + i0+tx];
    }
    __syncthreads();
    #pragma unroll
    for (int r=0;r<4;r++){
        int ii = ty+8*r;
        int l = (i0+ii)*64 + j0+tx;
        g_ycomb[offo + l] = g_ydir[off0 + l] + g_ydir[off1 + (LL-1-l)] + s[tx][ii];
    }
}

// ---------------- res[c][l] -> out flat (l*128 + c), via tile transpose -------
__global__ void k_resremap(float* __restrict__ outp)
{
    int b = blockIdx.z, c0 = blockIdx.y*32, l0 = blockIdx.x*32;
    int tx=threadIdx.x, ty=threadIdx.y;
    __shared__ float s[32][33];
    #pragma unroll
    for (int r=0;r<4;r++){
        int cl = ty+8*r;
        s[cl][tx] = g_res[(long)b*DM*LL + (long)(c0+cl)*LL + l0+tx];
    }
    __syncthreads();
    #pragma unroll
    for (int r=0;r<4;r++){
        int ll = ty+8*r;
        outp[(long)b*DM*LL + (long)(l0+ll)*DM + c0+tx] = s[tx][ll];
    }
}

// ---------------- batchnorm over (b,h,w) per channel --------------------------
__global__ void k_bnstats(const float* __restrict__ outp)
{
    int cc = blockIdx.x, tid = threadIdx.x;
    __shared__ float ss[256], sq[256];
    float a=0.f, q=0.f;
    for (int i=tid;i<2*LL;i+=256){
        float v = outp[(long)(i>>12)*DM*LL + (long)cc*LL + (i&(LL-1))];
        a+=v; q+=v*v;
    }
    ss[tid]=a; sq[tid]=q;
    __syncthreads();
    for (int st=128; st>0; st>>=1){
        if (tid<st){ ss[tid]+=ss[tid+st]; sq[tid]+=sq[tid+st]; }
        __syncthreads();
    }
    if (tid==0){
        float mu = ss[0]*(1.f/(2*LL));
        float var = sq[0]*(1.f/(2*LL)) - mu*mu;
        g_bnmu[cc]=mu; g_bnrv[cc]=rsqrtf(var+EPS);
    }
}

__global__ void k_bnapply(float* __restrict__ outp, const float* __restrict__ bg,
                          const float* __restrict__ bb)
{
    long gi = (long)blockIdx.x*256 + threadIdx.x;
    int cc = (int)((gi>>12)&127);
    outp[gi] = (outp[gi]-g_bnmu[cc])*g_bnrv[cc]*bg[cc] + bb[cc];
}

// ---------------- launcher ----------------------------------------------------
extern "C" void kernel_launch(void* const* d_in, const int* in_sizes, int n_in,
                              void* d_out, int out_size)
{
    const float* x1        = (const float*)d_in[0];
    const float* x2        = (const float*)d_in[1];
    const float* ln_g      = (const float*)d_in[2];
    const float* ln_b      = (const float*)d_in[3];
    const float* in_proj_w = (const float*)d_in[4];
    const float* conv_w    = (const float*)d_in[5];
    const float* conv_b    = (const float*)d_in[6];
    const float* xproj_w   = (const float*)d_in[7];
    const float* dtproj_w  = (const float*)d_in[8];
    const float* dtproj_b  = (const float*)d_in[9];
    const float* A_log     = (const float*)d_in[10];
    const float* Dvec      = (const float*)d_in[11];
    const float* out_proj_w= (const float*)d_in[12];
    const float* bn_g      = (const float*)d_in[13];
    const float* bn_b      = (const float*)d_in[14];
    float* outp = (float*)d_out;

    float *p_xn,*p_xz,*p_dm,*p_dblT,*p_ycomb,*p_feat,*p_dpp,*p_dp,*p_res;
    cudaGetSymbolAddress((void**)&p_xn,   g_xn);
    cudaGetSymbolAddress((void**)&p_xz,   g_xz);
    cudaGetSymbolAddress((void**)&p_dm,   g_xcv_dm);
    cudaGetSymbolAddress((void**)&p_dblT, g_dblT);
    cudaGetSymbolAddress((void**)&p_ycomb,g_ycomb);
    cudaGetSymbolAddress((void**)&p_feat, g_feat);
    cudaGetSymbolAddress((void**)&p_dpp,  g_dpp);
    cudaGetSymbolAddress((void**)&p_dp,   g_dp);
    cudaGetSymbolAddress((void**)&p_res,  g_res);

    dim3 blk8(32,8);

    // 1. layernorm -> xn[f,b,l,c]
    k_ln<<<dim3(128,2,2),256>>>(x1,x2,ln_g,ln_b);
    // 2. in_proj (NT): xz[fb][d2][l] = W(512x128) * xn[fb]^T
    gemm_nt128<<<dim3(32,8,4),256>>>(in_proj_w, p_xn, p_xz,
        512,4096,128, 128,128,4096,
        0L,1,1, (long)LL*DM,1,4, (long)512*LL);
    // 3. direction remap (dirs 1,2 only)
    k_remap<<<dim3(4,512,8),256>>>();
    // 4. causal conv + silu -> xcv_dm[z][d][t]
    k_conv<<<dim3(4,256,12),256>>>(conv_w, conv_b);
    // 5. xproj (NN): dblT[z][r][t] = xpw(40x256) * xcv_dm[z](256x4096)
    gemm_nn128<<<dim3(32,1,12),256>>>(xproj_w, p_dm, p_dblT,
        40,4096,256, 256,4096,4096,
        40L*DI,2,3, (long)DI*LL,1,12, 40L*LL);
    // 6. dt projection + softplus (smem-staged)
    k_dtproj<<<dim3(16,4,12),256>>>(dtproj_w, dtproj_b);
    // 7. chunked selective scan: local -> compose -> final
    k_scan1<<<dim3(NCH,16,12),256>>>(A_log);
    k_scan2<<<192,256>>>(A_log);
    k_scan3<<<dim3(NCH,16,12),256>>>(A_log, Dvec);
    // 8. combine 3 directions
    k_combine<<<dim3(4,256,4),blk8>>>();
    // 9. out_proj (NN): feat[fb][c][l] = opw(128x256) * ycomb[fb]
    gemm_nn128<<<dim3(32,2,4),256>>>(out_proj_w, p_ycomb, p_feat,
        128,4096,256, 256,4096,4096,
        0L,1,1, (long)DI*LL,1,4, (long)DM*LL);
    // 10. dp split-K + deterministic reduce
    k_dp<<<dim3(2,2,32),256>>>(p_feat, p_dpp);
    k_dpred<<<128,256>>>();
    // 11. res (NN): res[b][c][l] = dp[b](128x128) * Bf[b]
    gemm_nn128<<<dim3(32,2,2),256>>>(p_dp, p_feat + 2L*DM*LL, p_res,
        128,4096,128, 128,4096,4096,
        (long)DM*DM,1,2, (long)DM*LL,1,2, (long)DM*LL);
    // 12. remap res -> out layout (b, c', h, w) == flat (l*128 + c)
    k_resremap<<<dim3(128,4,2),blk8>>>(outp);
    // 13-14. batchnorm over (b,h,w)
    k_bnstats<<<128,256>>>(outp);
    k_bnapply<<<4096,256>>>(outp, bn_g, bn_b);
}

// round 14
// speedup vs baseline: 2.8471x; 1.1106x over previous
#include <cuda_runtime.h>
#include <math.h>

#define LL 4096
#define DM 128
#define DI 256
#define DS 16
#define NCH 32
#define CHL 128
#define EPS 1e-5f

// ---------------- scratch (static device allocations; allowed) ----------------
__device__ float g_xn   [2*2*LL*DM];     // [f][b][l][c]
__device__ float g_xz   [4*512*LL];      // [f*2+b][d2][l]
__device__ float g_xzd  [12*512*LL];     // [(f*3+dir)*2+b][d2][t]  (dirs 1,2 only)
__device__ float g_xcv_dm[12*DI*LL];     // [z][d][t]
__device__ float g_dblT [12*40*LL];      // [z][r][t]
__device__ float g_dt   [12*DI*LL];      // [z][d][t]
__device__ float g_ydir [12*DI*LL];      // [z][d][t]
__device__ float g_ycomb[4*DI*LL];       // [f*2+b][d][l]
__device__ float g_feat [4*DM*LL];       // [f*2+b][c][l]
__device__ float g_dpp  [64*DM*DM];      // split-K partials for dp (2 b x 32 ch)
__device__ float g_dp   [2*DM*DM];
__device__ float g_res  [2*DM*LL];
__device__ float g_bnmu [DM];
__device__ float g_bnrv [DM];
// chunked-scan state
__device__ float g_hloc [12*NCH*DI*DS];  // chunk-local h_out
__device__ float g_hin  [12*NCH*DI*DS];  // composed h at chunk entry
__device__ float g_sdt  [12*NCH*DI];     // sum of dt per chunk per d

// base of the direction-ordered xz stream for batch-z (dir0 aliases g_xz)
__device__ __forceinline__ const float* xz_base(int z){
    int dir = (z%6)>>1;
    if (dir==0){ int fb = (z/6)*2 + (z&1); return g_xz + (long)fb*512*LL; }
    return g_xzd + (long)z*512*LL;
}

// ---------------- layernorm over channels: x[b,c,l] -> xn[f,b,l,c] ------------
__global__ void k_ln(const float* __restrict__ x1, const float* __restrict__ x2,
                     const float* __restrict__ lg, const float* __restrict__ lb)
{
    __shared__ float s[DM][33];
    __shared__ float mu_s[32], rv_s[32];
    int f = blockIdx.z, b = blockIdx.y, l0 = blockIdx.x*32, tid = threadIdx.x;
    const float* x = (f==0 ? x1 : x2) + (long)b*DM*LL;
    for (int idx=tid; idx<DM*32; idx+=256){
        int c = idx>>5, li = idx&31;
        s[c][li] = x[(long)c*LL + l0+li];
    }
    __syncthreads();
    if (tid < 32){
        float sum=0.f, sq=0.f;
        #pragma unroll 8
        for (int c=0;c<DM;c++){ float v=s[c][tid]; sum+=v; sq+=v*v; }
        float mu = sum*(1.f/DM);
        float var = sq*(1.f/DM) - mu*mu;
        mu_s[tid]=mu; rv_s[tid]=rsqrtf(var+EPS);
    }
    __syncthreads();
    float* outp = g_xn + ((long)(f*2+b)*LL + l0)*DM;
    for (int idx=tid; idx<32*DM; idx+=256){
        int li = idx>>7, c = idx&127;
        outp[(long)li*DM + c] = (s[c][li]-mu_s[li])*rv_s[li]*lg[c] + lb[c];
    }
}

// ======== 64(M)x128(N)-tile SGEMM, 256 threads, 4x8/thread, double-buffered ===
// NT: C[M,N] = A[M,K] * B[N,K]^T
__global__ void gemm_nt128(const float* __restrict__ A, const float* __restrict__ B,
                           float* __restrict__ C, int M,int N,int K,
                           int lda,int ldb,int ldc,
                           long aS,int aDiv,int aMod, long bS,int bDiv,int bMod, long cS)
{
    int z = blockIdx.z;
    A += (long)((z/aDiv)%aMod)*aS;
    B += (long)((z/bDiv)%bMod)*bS;
    C += (long)z*cS;
    int tid = threadIdx.x;
    int m0 = blockIdx.y*64, n0 = blockIdx.x*128;
    int lr = tid>>2, lk4 = (tid&3)*4;
    int ty = tid>>4, tx = tid&15;
    __shared__ float As[16][68], Bs[16][132];
    float acc[4][8] = {};
    bool am = (m0+lr) < M;
    float4 pa = am ? *(const float4*)(A + (long)(m0+lr)*lda + lk4)
                   : make_float4(0.f,0.f,0.f,0.f);
    float4 pb0 = *(const float4*)(B + (long)(n0+lr)*ldb + lk4);
    float4 pb1 = *(const float4*)(B + (long)(n0+64+lr)*ldb + lk4);
    As[lk4+0][lr]=pa.x; As[lk4+1][lr]=pa.y; As[lk4+2][lr]=pa.z; As[lk4+3][lr]=pa.w;
    Bs[lk4+0][lr]=pb0.x; Bs[lk4+1][lr]=pb0.y; Bs[lk4+2][lr]=pb0.z; Bs[lk4+3][lr]=pb0.w;
    Bs[lk4+0][64+lr]=pb1.x; Bs[lk4+1][64+lr]=pb1.y; Bs[lk4+2][64+lr]=pb1.z; Bs[lk4+3][64+lr]=pb1.w;
    __syncthreads();
    for (int k0=16;k0<K;k0+=16){
        pa = am ? *(const float4*)(A + (long)(m0+lr)*lda + k0+lk4)
                : make_float4(0.f,0.f,0.f,0.f);
        pb0 = *(const float4*)(B + (long)(n0+lr)*ldb + k0+lk4);
        pb1 = *(const float4*)(B + (long)(n0+64+lr)*ldb + k0+lk4);
        #pragma unroll
        for (int kk=0;kk<16;kk++){
            float4 a  = *(const float4*)&As[kk][ty*4];
            float4 v0 = *(const float4*)&Bs[kk][tx*4];
            float4 v1 = *(const float4*)&Bs[kk][64+tx*4];
            float aa[4]={a.x,a.y,a.z,a.w};
            float bb[8]={v0.x,v0.y,v0.z,v0.w,v1.x,v1.y,v1.z,v1.w};
            #pragma unroll
            for (int i=0;i<4;i++)
                #pragma unroll
                for (int j=0;j<8;j++) acc[i][j] += aa[i]*bb[j];
        }
        __syncthreads();
        As[lk4+0][lr]=pa.x; As[lk4+1][lr]=pa.y; As[lk4+2][lr]=pa.z; As[lk4+3][lr]=pa.w;
        Bs[lk4+0][lr]=pb0.x; Bs[lk4+1][lr]=pb0.y; Bs[lk4+2][lr]=pb0.z; Bs[lk4+3][lr]=pb0.w;
        Bs[lk4+0][64+lr]=pb1.x; Bs[lk4+1][64+lr]=pb1.y; Bs[lk4+2][64+lr]=pb1.z; Bs[lk4+3][64+lr]=pb1.w;
        __syncthreads();
    }
    #pragma unroll
    for (int kk=0;kk<16;kk++){
        float4 a  = *(const float4*)&As[kk][ty*4];
        float4 v0 = *(const float4*)&Bs[kk][tx*4];
        float4 v1 = *(const float4*)&Bs[kk][64+tx*4];
        float aa[4]={a.x,a.y,a.z,a.w};
        float bb[8]={v0.x,v0.y,v0.z,v0.w,v1.x,v1.y,v1.z,v1.w};
        #pragma unroll
        for (int i=0;i<4;i++)
            #pragma unroll
            for (int j=0;j<8;j++) acc[i][j] += aa[i]*bb[j];
    }
    #pragma unroll
    for (int i=0;i<4;i++){
        int m = m0+ty*4+i;
        if (m < M){
            float4 o0 = make_float4(acc[i][0],acc[i][1],acc[i][2],acc[i][3]);
            float4 o1 = make_float4(acc[i][4],acc[i][5],acc[i][6],acc[i][7]);
            *(float4*)(C + (long)m*ldc + n0+tx*4)    = o0;
            *(float4*)(C + (long)m*ldc + n0+64+tx*4) = o1;
        }
    }
}

// NN: C[M,N] = A[M,K] * B[K,N], double-buffered
__global__ void gemm_nn128(const float* __restrict__ A, const float* __restrict__ B,
                           float* __restrict__ C, int M,int N,int K,
                           int lda,int ldb,int ldc,
                           long aS,int aDiv,int aMod, long bS,int bDiv,int bMod, long cS)
{
    int z = blockIdx.z;
    A += (long)((z/aDiv)%aMod)*aS;
    B += (long)((z/bDiv)%bMod)*bS;
    C += (long)z*cS;
    int tid = threadIdx.x;
    int m0 = blockIdx.y*64, n0 = blockIdx.x*128;
    int lr = tid>>2, lk4 = (tid&3)*4;
    int bk = tid>>5, bn4 = (tid&31)*4;
    int ty = tid>>4, tx = tid&15;
    __shared__ float As[16][68], Bs[16][132];
    float acc[4][8] = {};
    bool am = (m0+lr) < M;
    float4 pa = am ? *(const float4*)(A + (long)(m0+lr)*lda + lk4)
                   : make_float4(0.f,0.f,0.f,0.f);
    float4 pb0 = *(const float4*)(B + (long)bk*ldb + n0+bn4);
    float4 pb1 = *(const float4*)(B + (long)(bk+8)*ldb + n0+bn4);
    As[lk4+0][lr]=pa.x; As[lk4+1][lr]=pa.y; As[lk4+2][lr]=pa.z; As[lk4+3][lr]=pa.w;
    *(float4*)&Bs[bk][bn4]   = pb0;
    *(float4*)&Bs[bk+8][bn4] = pb1;
    __syncthreads();
    for (int k0=16;k0<K;k0+=16){
        pa = am ? *(const float4*)(A + (long)(m0+lr)*lda + k0+lk4)
                : make_float4(0.f,0.f,0.f,0.f);
        pb0 = *(const float4*)(B + (long)(k0+bk)*ldb + n0+bn4);
        pb1 = *(const float4*)(B + (long)(k0+bk+8)*ldb + n0+bn4);
        #pragma unroll
        for (int kk=0;kk<16;kk++){
            float4 a  = *(const float4*)&As[kk][ty*4];
            float4 v0 = *(const float4*)&Bs[kk][tx*4];
            float4 v1 = *(const float4*)&Bs[kk][64+tx*4];
            float aa[4]={a.x,a.y,a.z,a.w};
            float bb[8]={v0.x,v0.y,v0.z,v0.w,v1.x,v1.y,v1.z,v1.w};
            #pragma unroll
            for (int i=0;i<4;i++)
                #pragma unroll
                for (int j=0;j<8;j++) acc[i][j] += aa[i]*bb[j];
        }
        __syncthreads();
        As[lk4+0][lr]=pa.x; As[lk4+1][lr]=pa.y; As[lk4+2][lr]=pa.z; As[lk4+3][lr]=pa.w;
        *(float4*)&Bs[bk][bn4]   = pb0;
        *(float4*)&Bs[bk+8][bn4] = pb1;
        __syncthreads();
    }
    #pragma unroll
    for (int kk=0;kk<16;kk++){
        float4 a  = *(const float4*)&As[kk][ty*4];
        float4 v0 = *(const float4*)&Bs[kk][tx*4];
        float4 v1 = *(const float4*)&Bs[kk][64+tx*4];
        float aa[4]={a.x,a.y,a.z,a.w};
        float bb[8]={v0.x,v0.y,v0.z,v0.w,v1.x,v1.y,v1.z,v1.w};
        #pragma unroll
        for (int i=0;i<4;i++)
            #pragma unroll
            for (int j=0;j<8;j++) acc[i][j] += aa[i]*bb[j];
    }
    #pragma unroll
    for (int i=0;i<4;i++){
        int m = m0+ty*4+i;
        if (m < M){
            float4 o0 = make_float4(acc[i][0],acc[i][1],acc[i][2],acc[i][3]);
            float4 o1 = make_float4(acc[i][4],acc[i][5],acc[i][6],acc[i][7]);
            *(float4*)(C + (long)m*ldc + n0+tx*4)    = o0;
            *(float4*)(C + (long)m*ldc + n0+64+tx*4) = o1;
        }
    }
}

// ---------------- split-K dp (32 chunks of K=128), double-buffered ------------
__global__ void k_dp(const float* __restrict__ feat, float* __restrict__ dpp)
{
    int zz = blockIdx.z; int b = zz>>5, ch = zz&31;
    const float* A  = feat + (long)b    *DM*LL + ch*128;
    const float* Bp = feat + (long)(2+b)*DM*LL + ch*128;
    int tid = threadIdx.x;
    int tx = tid&15, ty = tid>>4;
    int n0 = blockIdx.x*64, m0 = blockIdx.y*64;
    int lm = tid>>2, lk4 = (tid&3)*4;
    __shared__ float As[16][68], Bs[16][68];
    float acc[4][4] = {};
    float4 pa = *(const float4*)(A  + (long)(m0+lm)*LL + lk4);
    float4 pb = *(const float4*)(Bp + (long)(n0+lm)*LL + lk4);
    As[lk4+0][lm]=pa.x; As[lk4+1][lm]=pa.y; As[lk4+2][lm]=pa.z; As[lk4+3][lm]=pa.w;
    Bs[lk4+0][lm]=pb.x; Bs[lk4+1][lm]=pb.y; Bs[lk4+2][lm]=pb.z; Bs[lk4+3][lm]=pb.w;
    __syncthreads();
    for (int k0=16;k0<128;k0+=16){
        pa = *(const float4*)(A  + (long)(m0+lm)*LL + k0+lk4);
        pb = *(const float4*)(Bp + (long)(n0+lm)*LL + k0+lk4);
        #pragma unroll
        for (int kk=0;kk<16;kk++){
            float4 a = *(const float4*)&As[kk][ty*4];
            float4 bv = *(const float4*)&Bs[kk][tx*4];
            float aa[4]={a.x,a.y,a.z,a.w}, bb[4]={bv.x,bv.y,bv.z,bv.w};
            #pragma unroll
            for (int i=0;i<4;i++)
                #pragma unroll
                for (int j=0;j<4;j++) acc[i][j] += aa[i]*bb[j];
        }
        __syncthreads();
        As[lk4+0][lm]=pa.x; As[lk4+1][lm]=pa.y; As[lk4+2][lm]=pa.z; As[lk4+3][lm]=pa.w;
        Bs[lk4+0][lm]=pb.x; Bs[lk4+1][lm]=pb.y; Bs[lk4+2][lm]=pb.z; Bs[lk4+3][lm]=pb.w;
        __syncthreads();
    }
    #pragma unroll
    for (int kk=0;kk<16;kk++){
        float4 a = *(const float4*)&As[kk][ty*4];
        float4 bv = *(const float4*)&Bs[kk][tx*4];
        float aa[4]={a.x,a.y,a.z,a.w}, bb[4]={bv.x,bv.y,bv.z,bv.w};
        #pragma unroll
        for (int i=0;i<4;i++)
            #pragma unroll
            for (int j=0;j<4;j++) acc[i][j] += aa[i]*bb[j];
    }
    float* Cp = dpp + (long)zz*DM*DM;
    #pragma unroll
    for (int i=0;i<4;i++)
        #pragma unroll
        for (int j=0;j<4;j++)
            Cp[(long)(m0+ty*4+i)*DM + n0+tx*4+j] = acc[i][j];
}

__global__ void k_dpred()
{
    int i = blockIdx.x*256 + threadIdx.x;   // 0..32767
    int b = i>>14, j = i&16383;
    float s = 0.f;
    #pragma unroll
    for (int ch=0;ch<32;ch++) s += g_dpp[(long)(b*32+ch)*DM*DM + j];
    g_dp[(long)b*DM*DM + j] = s;
}

// ---------------- direction remap: xz -> xzd (flip / 64x64 T); dirs 1,2 only --
__global__ void k_remap()
{
    int zr = blockIdx.z;
    int f = zr>>2, dirm = (zr>>1)&1, b = zr&1;
    int dir = 1+dirm;
    int z = (f*3+dir)*2+b;
    int fb = f*2+b;
    const float* src = g_xz  + (long)fb*512*LL;
    float*       dst = g_xzd + (long)z *512*LL;
    int d = blockIdx.y, tid = threadIdx.x;
    __shared__ float s[32][33];
    if (dir==1){
        int t = blockIdx.x*1024 + tid*4;
        const float* sr = src + (long)d*LL;
        float*       dw = dst + (long)d*LL;
        #pragma unroll
        for (int j=0;j<4;j++) dw[t+j] = sr[LL-1-(t+j)];
    } else {
        int a0 = (blockIdx.x&1)*32, b0 = (blockIdx.x>>1)*32;
        const float* sr = src + (long)d*LL;
        float*       dw = dst + (long)d*LL;
        #pragma unroll
        for (int q=0;q<4;q++){
            int idx = tid + q*256;
            int bb = idx>>5, aa = idx&31;
            s[bb][aa] = sr[(b0+bb)*64 + a0+aa];
        }
        __syncthreads();
        #pragma unroll
        for (int q=0;q<4;q++){
            int idx = tid + q*256;
            int aa = idx>>5, bb = idx&31;
            dw[(a0+aa)*64 + b0+bb] = s[bb][aa];
        }
    }
}

// ---------------- causal depthwise conv (DC=4) + silu, 4 t/thread -------------
__global__ void k_conv(const float* __restrict__ cw, const float* __restrict__ cb)
{
    int z = blockIdx.z;
    int dir = (z%6)>>1;
    int d = blockIdx.y;
    int t0 = (blockIdx.x*256 + threadIdx.x)*4;
    const float* row = xz_base(z) + (long)d*LL;
    float4 cur = *(const float4*)(row + t0);
    float p1,p2,p3;
    if (t0 >= 4){
        float4 pv = *(const float4*)(row + t0 - 4);
        p1=pv.y; p2=pv.z; p3=pv.w;
    } else { p1=p2=p3=0.f; }
    float xs[7] = {p1,p2,p3,cur.x,cur.y,cur.z,cur.w};
    float4 wv = *(const float4*)(cw + (long)(dir*DI + d)*4);
    float bias = cb[dir*DI + d];
    float out[4];
    #pragma unroll
    for (int j=0;j<4;j++){
        float a = bias + wv.x*xs[j] + wv.y*xs[j+1] + wv.z*xs[j+2] + wv.w*xs[j+3];
        out[j] = a / (1.f + __expf(-a));
    }
    *(float4*)(g_xcv_dm + (long)z*DI*LL + (long)d*LL + t0) =
        make_float4(out[0],out[1],out[2],out[3]);
}

// ---------------- dt = softplus(dpw @ dblT[:8] + dpb), smem-staged ------------
__global__ void k_dtproj(const float* __restrict__ dpw, const float* __restrict__ dpb)
{
    int z = blockIdx.z;
    int dir = (z%6)>>1;
    int t0 = blockIdx.x*256, d0 = blockIdx.y*64;
    int tid = threadIdx.x;
    __shared__ float sB[8][260];
    __shared__ float sWf[512];
    __shared__ float sBias[64];
    {   // stage B rows (8 x 256)
        int r = tid>>5, c = tid&31;
        const float* src = g_dblT + (long)z*40*LL + (long)r*LL + t0;
        *(float4*)&sB[r][c*4]     = *(const float4*)(src + c*4);
        *(float4*)&sB[r][128+c*4] = *(const float4*)(src + 128 + c*4);
    }
    if (tid < 128)
        *(float4*)&sWf[tid*4] = *(const float4*)(dpw + (long)(dir*DI + d0)*8 + tid*4);
    if (tid < 64)
        sBias[tid] = dpb[dir*DI + d0 + tid];
    __syncthreads();
    int dgrp = tid>>4, tg = tid&15;
    float w[4][8], bs[4];
    #pragma unroll
    for (int i=0;i<4;i++){
        bs[i] = sBias[dgrp*4+i];
        #pragma unroll
        for (int r=0;r<8;r++) w[i][r] = sWf[(dgrp*4+i)*8 + r];
    }
    float* dst = g_dt + (long)z*DI*LL;
    #pragma unroll 4
    for (int jj=0;jj<16;jj++){
        int tl = tg + 16*jj;
        float xv[8];
        #pragma unroll
        for (int r=0;r<8;r++) xv[r] = sB[r][tl];
        #pragma unroll
        for (int i=0;i<4;i++){
            float a = bs[i];
            #pragma unroll
            for (int r=0;r<8;r++) a += w[i][r]*xv[r];
            float sp = fmaxf(a,0.f) + log1pf(__expf(-fabsf(a)));
            dst[(long)(d0+dgrp*4+i)*LL + t0+tl] = sp;
        }
    }
}

// ======================= chunked selective scan ==============================
// Phase A: per-chunk local scan from h=0 -> g_hloc, plus per-chunk sum(dt).
// 128 threads, 32 d per block; lane owns 4 states (n = ngrp*4+i).
__global__ void k_scan1(const float* __restrict__ A_log)
{
    int z = blockIdx.z;
    int dir = (z%6)>>1;
    int d0 = blockIdx.y*32;
    int ch = blockIdx.x, c0 = ch*CHL;
    int tid = threadIdx.x;
    int lane = tid&31, warp = tid>>5;
    int ngrp = lane&3;
    int dl = warp*8 + (lane>>2);
    int d = d0+dl;
    float An[4];
    #pragma unroll
    for (int i=0;i<4;i++)
        An[i] = -__expf(A_log[(long)(dir*DI+d)*DS + ngrp*4+i]);

    const float* dtB = g_dt     + (long)z*DI*LL;
    const float* xB  = g_xcv_dm + (long)z*DI*LL;
    const float* dblT= g_dblT   + (long)z*40*LL;

    __shared__ float s_dt[32][129], s_x[32][129];
    __shared__ float s_B[128][16];

    for (int f4=tid; f4<1024; f4+=128){
        int r = f4>>5, c4 = (f4&31)*4;
        float4 v = *(const float4*)(dtB + (long)(d0+r)*LL + c0 + c4);
        s_dt[r][c4+0]=v.x; s_dt[r][c4+1]=v.y; s_dt[r][c4+2]=v.z; s_dt[r][c4+3]=v.w;
        float4 w = *(const float4*)(xB + (long)(d0+r)*LL + c0 + c4);
        s_x[r][c4+0]=w.x; s_x[r][c4+1]=w.y; s_x[r][c4+2]=w.z; s_x[r][c4+3]=w.w;
    }
    for (int f4=tid; f4<512; f4+=128){
        int n = f4>>5, tc = (f4&31)*4;
        float4 v = *(const float4*)(dblT + (long)(8+n)*LL + c0 + tc);
        s_B[tc+0][n]=v.x; s_B[tc+1][n]=v.y; s_B[tc+2][n]=v.z; s_B[tc+3][n]=v.w;
    }
    __syncthreads();

    float h0=0.f,h1=0.f,h2=0.f,h3=0.f, sdt=0.f;
    #pragma unroll 4
    for (int t=0;t<CHL;t++){
        float dtv = s_dt[dl][t];
        float xv  = s_x[dl][t];
        sdt += dtv;
        float4 Bv = *(const float4*)&s_B[t][ngrp*4];
        float bs = dtv*xv;
        h0 = __expf(dtv*An[0])*h0 + bs*Bv.x;
        h1 = __expf(dtv*An[1])*h1 + bs*Bv.y;
        h2 = __expf(dtv*An[2])*h2 + bs*Bv.z;
        h3 = __expf(dtv*An[3])*h3 + bs*Bv.w;
    }
    long base = ((long)(z*NCH+ch)*DI + d)*DS;
    *(float4*)(g_hloc + base + ngrp*4) = make_float4(h0,h1,h2,h3);
    if (ngrp==0) g_sdt[(long)(z*NCH+ch)*DI + d] = sdt;
}

// Phase B: compose chunk states serially (32 steps per (z,d,n))
__global__ void k_scan2(const float* __restrict__ A_log)
{
    int i = blockIdx.x*256 + threadIdx.x;      // 0..49151
    int z = i>>12, rem = i&4095;
    int d = rem>>4, n = rem&15;
    int dir = (z%6)>>1;
    float An = -__expf(A_log[(long)(dir*DI + d)*DS + n]);
    float h = 0.f;
    #pragma unroll 4
    for (int c=0;c<NCH;c++){
        long base = (long)(z*NCH+c)*DI + d;
        g_hin[base*DS + n] = h;
        float S = g_sdt[base];
        h = __expf(An*S)*h + g_hloc[base*DS + n];
    }
}

// Phase C: per-chunk full scan with y, from composed h_in.
// 128 threads, 32 d per block; 2-shfl reduction; y reuses s_dt rows.
__global__ void k_scan3(const float* __restrict__ A_log, const float* __restrict__ Dp)
{
    int z = blockIdx.z;
    int dir = (z%6)>>1;
    int d0 = blockIdx.y*32;
    int ch = blockIdx.x, c0 = ch*CHL;
    int tid = threadIdx.x;
    int lane = tid&31, warp = tid>>5;
    int ngrp = lane&3;
    int dl = warp*8 + (lane>>2);
    int d = d0+dl;
    float An[4];
    #pragma unroll
    for (int i=0;i<4;i++)
        An[i] = -__expf(A_log[(long)(dir*DI+d)*DS + ngrp*4+i]);

    const float* dtB = g_dt     + (long)z*DI*LL;
    const float* xB  = g_xcv_dm + (long)z*DI*LL;
    const float* dblT= g_dblT   + (long)z*40*LL;
    const float* zB  = xz_base(z) + (long)DI*LL;
    float* yB = g_ydir + (long)z*DI*LL;

    __shared__ float s_dt[32][129], s_x[32][129];   // s_dt rows become y
    __shared__ float s_B[64][16], s_C[64][16];

    for (int f4=tid; f4<1024; f4+=128){
        int r = f4>>5, c4 = (f4&31)*4;
        float4 v = *(const float4*)(dtB + (long)(d0+r)*LL + c0 + c4);
        s_dt[r][c4+0]=v.x; s_dt[r][c4+1]=v.y; s_dt[r][c4+2]=v.z; s_dt[r][c4+3]=v.w;
        float4 w = *(const float4*)(xB + (long)(d0+r)*LL + c0 + c4);
        s_x[r][c4+0]=w.x; s_x[r][c4+1]=w.y; s_x[r][c4+2]=w.z; s_x[r][c4+3]=w.w;
    }
    long hbase = ((long)(z*NCH+ch)*DI + d)*DS;
    float4 hv = *(const float4*)(g_hin + hbase + ngrp*4);
    float h0=hv.x, h1=hv.y, h2=hv.z, h3=hv.w;

    #pragma unroll
    for (int half=0; half<2; half++){
        __syncthreads();
        for (int f4=tid; f4<256; f4+=128){
            int n = f4>>4, tc = (f4&15)*4;
            float4 v = *(const float4*)(dblT + (long)(8+n)*LL  + c0 + half*64 + tc);
            s_B[tc+0][n]=v.x; s_B[tc+1][n]=v.y; s_B[tc+2][n]=v.z; s_B[tc+3][n]=v.w;
            float4 w = *(const float4*)(dblT + (long)(24+n)*LL + c0 + half*64 + tc);
            s_C[tc+0][n]=w.x; s_C[tc+1][n]=w.y; s_C[tc+2][n]=w.z; s_C[tc+3][n]=w.w;
        }
        __syncthreads();
        int tbase = half*64;
        #pragma unroll 4
        for (int tt=0; tt<64; tt++){
            int t = tbase+tt;
            float dtv = s_dt[dl][t];
            float xv  = s_x[dl][t];
            float4 Bv = *(const float4*)&s_B[tt][ngrp*4];
            float4 Cv = *(const float4*)&s_C[tt][ngrp*4];
            float bs = dtv*xv;
            h0 = __expf(dtv*An[0])*h0 + bs*Bv.x;
            h1 = __expf(dtv*An[1])*h1 + bs*Bv.y;
            h2 = __expf(dtv*An[2])*h2 + bs*Bv.z;
            h3 = __expf(dtv*An[3])*h3 + bs*Bv.w;
            float p = h0*Cv.x + h1*Cv.y + h2*Cv.z + h3*Cv.w;
            p += __shfl_xor_sync(0xffffffffu, p, 1);
            p += __shfl_xor_sync(0xffffffffu, p, 2);
            if (ngrp==0) s_dt[dl][t] = p;     // dt(t) already consumed
        }
    }
    __syncthreads();
    float Dd = Dp[dir*DI + d0];   // dummy init; real value loaded per row below
    (void)Dd;
    for (int k=0;k<32;k++){
        int r = k, cc = tid;
        float zv = zB[(long)(d0+r)*LL + c0+cc];
        float sz = zv / (1.f + __expf(-zv));
        float yv = (s_dt[r][cc] + Dp[dir*DI+d0+r]*s_x[r][cc]) * sz;
        yB[(long)(d0+r)*LL + c0+cc] = yv;
    }
}

// ---------------- combine 3 directions (fwd + flip + 64x64 transpose) ---------
__global__ void k_combine()
{
    int z2 = blockIdx.z, d = blockIdx.y;
    int f = z2>>1, b = z2&1;
    long off0 = ((long)((f*3+0)*2+b)*DI + d)*LL;
    long off1 = ((long)((f*3+1)*2+b)*DI + d)*LL;
    long off2 = ((long)((f*3+2)*2+b)*DI + d)*LL;
    long offo = ((long)z2*DI + d)*LL;
    int i0 = (blockIdx.x&1)*32, j0 = (blockIdx.x>>1)*32;
    int tx=threadIdx.x, ty=threadIdx.y;
    __shared__ float s[32][33];
    #pragma unroll
    for (int r=0;r<4;r++){
        int jj = ty+8*r;
        s[jj][tx] = g_ydir[off2 + (j0+jj)*64 + i0+tx];
    }
    __syncthreads();
    #pragma unroll
    for (int r=0;r<4;r++){
        int ii = ty+8*r;
        int l = (i0+ii)*64 + j0+tx;
        g_ycomb[offo + l] = g_ydir[off0 + l] + g_ydir[off1 + (LL-1-l)] + s[tx][ii];
    }
}

// ---------------- res[c][l] -> out flat (l*128 + c), via tile transpose -------
__global__ void k_resremap(float* __restrict__ outp)
{
    int b = blockIdx.z, c0 = blockIdx.y*32, l0 = blockIdx.x*32;
    int tx=threadIdx.x, ty=threadIdx.y;
    __shared__ float s[32][33];
    #pragma unroll
    for (int r=0;r<4;r++){
        int cl = ty+8*r;
        s[cl][tx] = g_res[(long)b*DM*LL + (long)(c0+cl)*LL + l0+tx];
    }
    __syncthreads();
    #pragma unroll
    for (int r=0;r<4;r++){
        int ll = ty+8*r;
        outp[(long)b*DM*LL + (long)(l0+ll)*DM + c0+tx] = s[tx][ll];
    }
}

// ---------------- batchnorm over (b,h,w) per channel --------------------------
__global__ void k_bnstats(const float* __restrict__ outp)
{
    int cc = blockIdx.x, tid = threadIdx.x;
    __shared__ float ss[256], sq[256];
    float a=0.f, q=0.f;
    for (int i=tid;i<2*LL;i+=256){
        float v = outp[(long)(i>>12)*DM*LL + (long)cc*LL + (i&(LL-1))];
        a+=v; q+=v*v;
    }
    ss[tid]=a; sq[tid]=q;
    __syncthreads();
    for (int st=128; st>0; st>>=1){
        if (tid<st){ ss[tid]+=ss[tid+st]; sq[tid]+=sq[tid+st]; }
        __syncthreads();
    }
    if (tid==0){
        float mu = ss[0]*(1.f/(2*LL));
        float var = sq[0]*(1.f/(2*LL)) - mu*mu;
        g_bnmu[cc]=mu; g_bnrv[cc]=rsqrtf(var+EPS);
    }
}

__global__ void k_bnapply(float* __restrict__ outp, const float* __restrict__ bg,
                          const float* __restrict__ bb)
{
    long gi = (long)blockIdx.x*256 + threadIdx.x;
    int cc = (int)((gi>>12)&127);
    outp[gi] = (outp[gi]-g_bnmu[cc])*g_bnrv[cc]*bg[cc] + bb[cc];
}

// ---------------- launcher ----------------------------------------------------
extern "C" void kernel_launch(void* const* d_in, const int* in_sizes, int n_in,
                              void* d_out, int out_size)
{
    const float* x1        = (const float*)d_in[0];
    const float* x2        = (const float*)d_in[1];
    const float* ln_g      = (const float*)d_in[2];
    const float* ln_b      = (const float*)d_in[3];
    const float* in_proj_w = (const float*)d_in[4];
    const float* conv_w    = (const float*)d_in[5];
    const float* conv_b    = (const float*)d_in[6];
    const float* xproj_w   = (const float*)d_in[7];
    const float* dtproj_w  = (const float*)d_in[8];
    const float* dtproj_b  = (const float*)d_in[9];
    const float* A_log     = (const float*)d_in[10];
    const float* Dvec      = (const float*)d_in[11];
    const float* out_proj_w= (const float*)d_in[12];
    const float* bn_g      = (const float*)d_in[13];
    const float* bn_b      = (const float*)d_in[14];
    float* outp = (float*)d_out;

    float *p_xn,*p_xz,*p_dm,*p_dblT,*p_ycomb,*p_feat,*p_dpp,*p_dp,*p_res;
    cudaGetSymbolAddress((void**)&p_xn,   g_xn);
    cudaGetSymbolAddress((void**)&p_xz,   g_xz);
    cudaGetSymbolAddress((void**)&p_dm,   g_xcv_dm);
    cudaGetSymbolAddress((void**)&p_dblT, g_dblT);
    cudaGetSymbolAddress((void**)&p_ycomb,g_ycomb);
    cudaGetSymbolAddress((void**)&p_feat, g_feat);
    cudaGetSymbolAddress((void**)&p_dpp,  g_dpp);
    cudaGetSymbolAddress((void**)&p_dp,   g_dp);
    cudaGetSymbolAddress((void**)&p_res,  g_res);

    dim3 blk8(32,8);

    // 1. layernorm -> xn[f,b,l,c]
    k_ln<<<dim3(128,2,2),256>>>(x1,x2,ln_g,ln_b);
    // 2. in_proj (NT): xz[fb][d2][l] = W(512x128) * xn[fb]^T
    gemm_nt128<<<dim3(32,8,4),256>>>(in_proj_w, p_xn, p_xz,
        512,4096,128, 128,128,4096,
        0L,1,1, (long)LL*DM,1,4, (long)512*LL);
    // 3. direction remap (dirs 1,2 only)
    k_remap<<<dim3(4,512,8),256>>>();
    // 4. causal conv + silu -> xcv_dm[z][d][t]
    k_conv<<<dim3(4,256,12),256>>>(conv_w, conv_b);
    // 5. xproj (NN): dblT[z][r][t] = xpw(40x256) * xcv_dm[z](256x4096)
    gemm_nn128<<<dim3(32,1,12),256>>>(xproj_w, p_dm, p_dblT,
        40,4096,256, 256,4096,4096,
        40L*DI,2,3, (long)DI*LL,1,12, 40L*LL);
    // 6. dt projection + softplus (smem-staged)
    k_dtproj<<<dim3(16,4,12),256>>>(dtproj_w, dtproj_b);
    // 7. chunked selective scan: local -> compose -> final
    k_scan1<<<dim3(NCH,8,12),128>>>(A_log);
    k_scan2<<<192,256>>>(A_log);
    k_scan3<<<dim3(NCH,8,12),128>>>(A_log, Dvec);
    // 8. combine 3 directions
    k_combine<<<dim3(4,256,4),blk8>>>();
    // 9. out_proj (NN): feat[fb][c][l] = opw(128x256) * ycomb[fb]
    gemm_nn128<<<dim3(32,2,4),256>>>(out_proj_w, p_ycomb, p_feat,
        128,4096,256, 256,4096,4096,
        0L,1,1, (long)DI*LL,1,4, (long)DM*LL);
    // 10. dp split-K (32 chunks) + deterministic reduce
    k_dp<<<dim3(2,2,64),256>>>(p_feat, p_dpp);
    k_dpred<<<128,256>>>();
    // 11. res (NN): res[b][c][l] = dp[b](128x128) * Bf[b]
    gemm_nn128<<<dim3(32,2,2),256>>>(p_dp, p_feat + 2L*DM*LL, p_res,
        128,4096,128, 128,4096,4096,
        (long)DM*DM,1,2, (long)DM*LL,1,2, (long)DM*LL);
    // 12. remap res -> out layout (b, c', h, w) == flat (l*128 + c)
    k_resremap<<<dim3(128,4,2),blk8>>>(outp);
    // 13-14. batchnorm over (b,h,w)
    k_bnstats<<<128,256>>>(outp);
    k_bnapply<<<4096,256>>>(outp, bn_g, bn_b);
}

// round 15
// speedup vs baseline: 3.2143x; 1.1290x over previous
#include <cuda_runtime.h>
#include <math.h>

#define LL 4096
#define DM 128
#define DI 256
#define DS 16
#define NCH 32
#define CHL 128
#define EPS 1e-5f

// ---------------- scratch (static device allocations; allowed) ----------------
__device__ float g_xn   [2*2*LL*DM];     // [f][b][l][c]
__device__ float g_xz   [4*512*LL];      // [f*2+b][d2][l]
__device__ float g_xzd  [12*512*LL];     // [(f*3+dir)*2+b][d2][t]  (dirs 1,2 only)
__device__ float g_xcv_dm[12*DI*LL];     // [z][d][t]
__device__ float g_dblT [12*40*LL];      // [z][r][t]
__device__ float g_dt   [12*DI*LL];      // [z][d][t]
__device__ float g_ydir [12*DI*LL];      // [z][d][t]
__device__ float g_ycomb[4*DI*LL];       // [f*2+b][d][l]
__device__ float g_feat [4*DM*LL];       // [f*2+b][c][l]
__device__ float g_dpp  [64*DM*DM];      // split-K partials for dp (2 b x 32 ch)
__device__ float g_dp   [2*DM*DM];
__device__ float g_res  [2*DM*LL];
__device__ float g_bnmu [DM];
__device__ float g_bnrv [DM];
// chunked-scan state
__device__ float g_hloc [12*NCH*DI*DS];  // chunk-local h_out
__device__ float g_hin  [12*NCH*DI*DS];  // composed h at chunk entry
__device__ float g_sdt  [12*NCH*DI];     // sum of dt per chunk per d

// base of the direction-ordered xz stream for batch-z (dir0 aliases g_xz)
__device__ __forceinline__ const float* xz_base(int z){
    int dir = (z%6)>>1;
    if (dir==0){ int fb = (z/6)*2 + (z&1); return g_xz + (long)fb*512*LL; }
    return g_xzd + (long)z*512*LL;
}

// ---------------- tf32 mma helpers -------------------------------------------
__device__ __forceinline__ unsigned f2tf(float x){
    unsigned r; asm("cvt.rna.tf32.f32 %0, %1;" : "=r"(r) : "f"(x)); return r;
}
__device__ __forceinline__ void mma_tf32(float* c, const unsigned* a, const unsigned* b){
    asm volatile(
        "mma.sync.aligned.m16n8k8.row.col.f32.tf32.tf32.f32 "
        "{%0,%1,%2,%3}, {%4,%5,%6,%7}, {%8,%9}, {%0,%1,%2,%3};\n"
        : "+f"(c[0]), "+f"(c[1]), "+f"(c[2]), "+f"(c[3])
        : "r"(a[0]), "r"(a[1]), "r"(a[2]), "r"(a[3]), "r"(b[0]), "r"(b[1]));
}

// ---------------- layernorm over channels: x[b,c,l] -> xn[f,b,l,c] ------------
__global__ void k_ln(const float* __restrict__ x1, const float* __restrict__ x2,
                     const float* __restrict__ lg, const float* __restrict__ lb)
{
    __shared__ float s[DM][33];
    __shared__ float mu_s[32], rv_s[32];
    int f = blockIdx.z, b = blockIdx.y, l0 = blockIdx.x*32, tid = threadIdx.x;
    const float* x = (f==0 ? x1 : x2) + (long)b*DM*LL;
    for (int idx=tid; idx<DM*32; idx+=256){
        int c = idx>>5, li = idx&31;
        s[c][li] = x[(long)c*LL + l0+li];
    }
    __syncthreads();
    if (tid < 32){
        float sum=0.f, sq=0.f;
        #pragma unroll 8
        for (int c=0;c<DM;c++){ float v=s[c][tid]; sum+=v; sq+=v*v; }
        float mu = sum*(1.f/DM);
        float var = sq*(1.f/DM) - mu*mu;
        mu_s[tid]=mu; rv_s[tid]=rsqrtf(var+EPS);
    }
    __syncthreads();
    float* outp = g_xn + ((long)(f*2+b)*LL + l0)*DM;
    for (int idx=tid; idx<32*DM; idx+=256){
        int li = idx>>7, c = idx&127;
        outp[(long)li*DM + c] = (s[c][li]-mu_s[li])*rv_s[li]*lg[c] + lb[c];
    }
}

// ======== tf32 tensor-core GEMM, tile 64(M)x128(N), 256 threads ===============
// Shared compute core over staged sA[16][72] (k x m) and sB[16][136] (k x n).
// warp tile 32x32: 2 m-subtiles x 4 n-subtiles of m16n8k8.
#define TF32_COMPUTE_STAGE() \
    { \
        _Pragma("unroll") \
        for (int kk=0;kk<16;kk+=8){ \
            unsigned af[2][4], bf[4][2]; \
            _Pragma("unroll") \
            for (int mi=0;mi<2;mi++){ \
                af[mi][0] = sA[kk+q][mw+mi*16+g]; \
                af[mi][1] = sA[kk+q][mw+mi*16+g+8]; \
                af[mi][2] = sA[kk+q+4][mw+mi*16+g]; \
                af[mi][3] = sA[kk+q+4][mw+mi*16+g+8]; \
            } \
            _Pragma("unroll") \
            for (int ni=0;ni<4;ni++){ \
                bf[ni][0] = sB[kk+q][nw+ni*8+g]; \
                bf[ni][1] = sB[kk+q+4][nw+ni*8+g]; \
            } \
            _Pragma("unroll") \
            for (int mi=0;mi<2;mi++) \
                _Pragma("unroll") \
                for (int ni=0;ni<4;ni++) \
                    mma_tf32(cacc[mi][ni], af[mi], bf[ni]); \
        } \
    }

#define TF32_STORE_C() \
    { \
        _Pragma("unroll") \
        for (int mi=0;mi<2;mi++){ \
            _Pragma("unroll") \
            for (int ni=0;ni<4;ni++){ \
                int m = m0 + mw + mi*16 + g; \
                int n = n0 + nw + ni*8 + 2*q; \
                if (m < M) \
                    *(float2*)(C + (long)m*ldc + n) = make_float2(cacc[mi][ni][0], cacc[mi][ni][1]); \
                if (m+8 < M) \
                    *(float2*)(C + (long)(m+8)*ldc + n) = make_float2(cacc[mi][ni][2], cacc[mi][ni][3]); \
            } \
        } \
    }

// NT: C[M,N] = A[M,K] * B[N,K]^T   (A,B K-contiguous)
__global__ void tgemm_nt(const float* __restrict__ A, const float* __restrict__ B,
                         float* __restrict__ C, int M,int N,int K,
                         int lda,int ldb,int ldc,
                         long aS,int aDiv,int aMod, long bS,int bDiv,int bMod, long cS)
{
    int z = blockIdx.z;
    A += (long)((z/aDiv)%aMod)*aS;
    B += (long)((z/bDiv)%bMod)*bS;
    C += (long)z*cS;
    int tid = threadIdx.x;
    int m0 = blockIdx.y*64, n0 = blockIdx.x*128;
    int lr = tid>>2, lk4 = (tid&3)*4;
    int warp = tid>>5, lane = tid&31;
    int g = lane>>2, q = lane&3;
    int mw = (warp>>2)*32, nw = (warp&3)*32;
    __shared__ unsigned sA[16][72];
    __shared__ unsigned sB[16][136];
    float cacc[2][4][4] = {};
    bool am = (m0+lr) < M;
    float4 pa = am ? *(const float4*)(A + (long)(m0+lr)*lda + lk4)
                   : make_float4(0.f,0.f,0.f,0.f);
    float4 pb0 = *(const float4*)(B + (long)(n0+lr)*ldb + lk4);
    float4 pb1 = *(const float4*)(B + (long)(n0+64+lr)*ldb + lk4);
    sA[lk4+0][lr]=f2tf(pa.x); sA[lk4+1][lr]=f2tf(pa.y); sA[lk4+2][lr]=f2tf(pa.z); sA[lk4+3][lr]=f2tf(pa.w);
    sB[lk4+0][lr]=f2tf(pb0.x); sB[lk4+1][lr]=f2tf(pb0.y); sB[lk4+2][lr]=f2tf(pb0.z); sB[lk4+3][lr]=f2tf(pb0.w);
    sB[lk4+0][64+lr]=f2tf(pb1.x); sB[lk4+1][64+lr]=f2tf(pb1.y); sB[lk4+2][64+lr]=f2tf(pb1.z); sB[lk4+3][64+lr]=f2tf(pb1.w);
    __syncthreads();
    for (int k0=16;k0<K;k0+=16){
        pa = am ? *(const float4*)(A + (long)(m0+lr)*lda + k0+lk4)
                : make_float4(0.f,0.f,0.f,0.f);
        pb0 = *(const float4*)(B + (long)(n0+lr)*ldb + k0+lk4);
        pb1 = *(const float4*)(B + (long)(n0+64+lr)*ldb + k0+lk4);
        TF32_COMPUTE_STAGE();
        __syncthreads();
        sA[lk4+0][lr]=f2tf(pa.x); sA[lk4+1][lr]=f2tf(pa.y); sA[lk4+2][lr]=f2tf(pa.z); sA[lk4+3][lr]=f2tf(pa.w);
        sB[lk4+0][lr]=f2tf(pb0.x); sB[lk4+1][lr]=f2tf(pb0.y); sB[lk4+2][lr]=f2tf(pb0.z); sB[lk4+3][lr]=f2tf(pb0.w);
        sB[lk4+0][64+lr]=f2tf(pb1.x); sB[lk4+1][64+lr]=f2tf(pb1.y); sB[lk4+2][64+lr]=f2tf(pb1.z); sB[lk4+3][64+lr]=f2tf(pb1.w);
        __syncthreads();
    }
    TF32_COMPUTE_STAGE();
    TF32_STORE_C();
}

// NN: C[M,N] = A[M,K] * B[K,N]   (A K-contig, B N-contig)
__global__ void tgemm_nn(const float* __restrict__ A, const float* __restrict__ B,
                         float* __restrict__ C, int M,int N,int K,
                         int lda,int ldb,int ldc,
                         long aS,int aDiv,int aMod, long bS,int bDiv,int bMod, long cS)
{
    int z = blockIdx.z;
    A += (long)((z/aDiv)%aMod)*aS;
    B += (long)((z/bDiv)%bMod)*bS;
    C += (long)z*cS;
    int tid = threadIdx.x;
    int m0 = blockIdx.y*64, n0 = blockIdx.x*128;
    int lr = tid>>2, lk4 = (tid&3)*4;
    int bk = tid>>5, bn4 = (tid&31)*4;
    int warp = tid>>5, lane = tid&31;
    int g = lane>>2, q = lane&3;
    int mw = (warp>>2)*32, nw = (warp&3)*32;
    __shared__ unsigned sA[16][72];
    __shared__ unsigned sB[16][136];
    float cacc[2][4][4] = {};
    bool am = (m0+lr) < M;
    float4 pa = am ? *(const float4*)(A + (long)(m0+lr)*lda + lk4)
                   : make_float4(0.f,0.f,0.f,0.f);
    float4 pb0 = *(const float4*)(B + (long)bk*ldb + n0+bn4);
    float4 pb1 = *(const float4*)(B + (long)(bk+8)*ldb + n0+bn4);
    sA[lk4+0][lr]=f2tf(pa.x); sA[lk4+1][lr]=f2tf(pa.y); sA[lk4+2][lr]=f2tf(pa.z); sA[lk4+3][lr]=f2tf(pa.w);
    {
        uint4 u0 = make_uint4(f2tf(pb0.x),f2tf(pb0.y),f2tf(pb0.z),f2tf(pb0.w));
        uint4 u1 = make_uint4(f2tf(pb1.x),f2tf(pb1.y),f2tf(pb1.z),f2tf(pb1.w));
        *(uint4*)&sB[bk][bn4]   = u0;
        *(uint4*)&sB[bk+8][bn4] = u1;
    }
    __syncthreads();
    for (int k0=16;k0<K;k0+=16){
        pa = am ? *(const float4*)(A + (long)(m0+lr)*lda + k0+lk4)
                : make_float4(0.f,0.f,0.f,0.f);
        pb0 = *(const float4*)(B + (long)(k0+bk)*ldb + n0+bn4);
        pb1 = *(const float4*)(B + (long)(k0+bk+8)*ldb + n0+bn4);
        TF32_COMPUTE_STAGE();
        __syncthreads();
        sA[lk4+0][lr]=f2tf(pa.x); sA[lk4+1][lr]=f2tf(pa.y); sA[lk4+2][lr]=f2tf(pa.z); sA[lk4+3][lr]=f2tf(pa.w);
        {
            uint4 u0 = make_uint4(f2tf(pb0.x),f2tf(pb0.y),f2tf(pb0.z),f2tf(pb0.w));
            uint4 u1 = make_uint4(f2tf(pb1.x),f2tf(pb1.y),f2tf(pb1.z),f2tf(pb1.w));
            *(uint4*)&sB[bk][bn4]   = u0;
            *(uint4*)&sB[bk+8][bn4] = u1;
        }
        __syncthreads();
    }
    TF32_COMPUTE_STAGE();
    TF32_STORE_C();
}

// ---------------- split-K dp (32 chunks of K=128), fp32, double-buffered ------
__global__ void k_dp(const float* __restrict__ feat, float* __restrict__ dpp)
{
    int zz = blockIdx.z; int b = zz>>5, ch = zz&31;
    const float* A  = feat + (long)b    *DM*LL + ch*128;
    const float* Bp = feat + (long)(2+b)*DM*LL + ch*128;
    int tid = threadIdx.x;
    int tx = tid&15, ty = tid>>4;
    int n0 = blockIdx.x*64, m0 = blockIdx.y*64;
    int lm = tid>>2, lk4 = (tid&3)*4;
    __shared__ float As[16][68], Bs[16][68];
    float acc[4][4] = {};
    float4 pa = *(const float4*)(A  + (long)(m0+lm)*LL + lk4);
    float4 pb = *(const float4*)(Bp + (long)(n0+lm)*LL + lk4);
    As[lk4+0][lm]=pa.x; As[lk4+1][lm]=pa.y; As[lk4+2][lm]=pa.z; As[lk4+3][lm]=pa.w;
    Bs[lk4+0][lm]=pb.x; Bs[lk4+1][lm]=pb.y; Bs[lk4+2][lm]=pb.z; Bs[lk4+3][lm]=pb.w;
    __syncthreads();
    for (int k0=16;k0<128;k0+=16){
        pa = *(const float4*)(A  + (long)(m0+lm)*LL + k0+lk4);
        pb = *(const float4*)(Bp + (long)(n0+lm)*LL + k0+lk4);
        #pragma unroll
        for (int kk=0;kk<16;kk++){
            float4 a = *(const float4*)&As[kk][ty*4];
            float4 bv = *(const float4*)&Bs[kk][tx*4];
            float aa[4]={a.x,a.y,a.z,a.w}, bb[4]={bv.x,bv.y,bv.z,bv.w};
            #pragma unroll
            for (int i=0;i<4;i++)
                #pragma unroll
                for (int j=0;j<4;j++) acc[i][j] += aa[i]*bb[j];
        }
        __syncthreads();
        As[lk4+0][lm]=pa.x; As[lk4+1][lm]=pa.y; As[lk4+2][lm]=pa.z; As[lk4+3][lm]=pa.w;
        Bs[lk4+0][lm]=pb.x; Bs[lk4+1][lm]=pb.y; Bs[lk4+2][lm]=pb.z; Bs[lk4+3][lm]=pb.w;
        __syncthreads();
    }
    #pragma unroll
    for (int kk=0;kk<16;kk++){
        float4 a = *(const float4*)&As[kk][ty*4];
        float4 bv = *(const float4*)&Bs[kk][tx*4];
        float aa[4]={a.x,a.y,a.z,a.w}, bb[4]={bv.x,bv.y,bv.z,bv.w};
        #pragma unroll
        for (int i=0;i<4;i++)
            #pragma unroll
            for (int j=0;j<4;j++) acc[i][j] += aa[i]*bb[j];
    }
    float* Cp = dpp + (long)zz*DM*DM;
    #pragma unroll
    for (int i=0;i<4;i++)
        #pragma unroll
        for (int j=0;j<4;j++)
            Cp[(long)(m0+ty*4+i)*DM + n0+tx*4+j] = acc[i][j];
}

__global__ void k_dpred()
{
    int i = blockIdx.x*256 + threadIdx.x;   // 0..32767
    int b = i>>14, j = i&16383;
    float s = 0.f;
    #pragma unroll
    for (int ch=0;ch<32;ch++) s += g_dpp[(long)(b*32+ch)*DM*DM + j];
    g_dp[(long)b*DM*DM + j] = s;
}

// ---------------- direction remap: xz -> xzd (flip / 64x64 T); dirs 1,2 only --
__global__ void k_remap()
{
    int zr = blockIdx.z;
    int f = zr>>2, dirm = (zr>>1)&1, b = zr&1;
    int dir = 1+dirm;
    int z = (f*3+dir)*2+b;
    int fb = f*2+b;
    const float* src = g_xz  + (long)fb*512*LL;
    float*       dst = g_xzd + (long)z *512*LL;
    int d = blockIdx.y, tid = threadIdx.x;
    __shared__ float s[32][33];
    if (dir==1){
        int t = blockIdx.x*1024 + tid*4;
        const float* sr = src + (long)d*LL;
        float*       dw = dst + (long)d*LL;
        #pragma unroll
        for (int j=0;j<4;j++) dw[t+j] = sr[LL-1-(t+j)];
    } else {
        int a0 = (blockIdx.x&1)*32, b0 = (blockIdx.x>>1)*32;
        const float* sr = src + (long)d*LL;
        float*       dw = dst + (long)d*LL;
        #pragma unroll
        for (int q=0;q<4;q++){
            int idx = tid + q*256;
            int bb = idx>>5, aa = idx&31;
            s[bb][aa] = sr[(b0+bb)*64 + a0+aa];
        }
        __syncthreads();
        #pragma unroll
        for (int q=0;q<4;q++){
            int idx = tid + q*256;
            int aa = idx>>5, bb = idx&31;
            dw[(a0+aa)*64 + b0+bb] = s[bb][aa];
        }
    }
}

// ---------------- causal depthwise conv (DC=4) + silu, 4 t/thread -------------
__global__ void k_conv(const float* __restrict__ cw, const float* __restrict__ cb)
{
    int z = blockIdx.z;
    int dir = (z%6)>>1;
    int d = blockIdx.y;
    int t0 = (blockIdx.x*256 + threadIdx.x)*4;
    const float* row = xz_base(z) + (long)d*LL;
    float4 cur = *(const float4*)(row + t0);
    float p1,p2,p3;
    if (t0 >= 4){
        float4 pv = *(const float4*)(row + t0 - 4);
        p1=pv.y; p2=pv.z; p3=pv.w;
    } else { p1=p2=p3=0.f; }
    float xs[7] = {p1,p2,p3,cur.x,cur.y,cur.z,cur.w};
    float4 wv = *(const float4*)(cw + (long)(dir*DI + d)*4);
    float bias = cb[dir*DI + d];
    float out[4];
    #pragma unroll
    for (int j=0;j<4;j++){
        float a = bias + wv.x*xs[j] + wv.y*xs[j+1] + wv.z*xs[j+2] + wv.w*xs[j+3];
        out[j] = a / (1.f + __expf(-a));
    }
    *(float4*)(g_xcv_dm + (long)z*DI*LL + (long)d*LL + t0) =
        make_float4(out[0],out[1],out[2],out[3]);
}

// ---------------- dt = softplus(dpw @ dblT[:8] + dpb), smem-staged ------------
__global__ void k_dtproj(const float* __restrict__ dpw, const float* __restrict__ dpb)
{
    int z = blockIdx.z;
    int dir = (z%6)>>1;
    int t0 = blockIdx.x*256, d0 = blockIdx.y*64;
    int tid = threadIdx.x;
    __shared__ float sB[8][260];
    __shared__ float sWf[512];
    __shared__ float sBias[64];
    {   // stage B rows (8 x 256)
        int r = tid>>5, c = tid&31;
        const float* src = g_dblT + (long)z*40*LL + (long)r*LL + t0;
        *(float4*)&sB[r][c*4]     = *(const float4*)(src + c*4);
        *(float4*)&sB[r][128+c*4] = *(const float4*)(src + 128 + c*4);
    }
    if (tid < 128)
        *(float4*)&sWf[tid*4] = *(const float4*)(dpw + (long)(dir*DI + d0)*8 + tid*4);
    if (tid < 64)
        sBias[tid] = dpb[dir*DI + d0 + tid];
    __syncthreads();
    int dgrp = tid>>4, tg = tid&15;
    float w[4][8], bs[4];
    #pragma unroll
    for (int i=0;i<4;i++){
        bs[i] = sBias[dgrp*4+i];
        #pragma unroll
        for (int r=0;r<8;r++) w[i][r] = sWf[(dgrp*4+i)*8 + r];
    }
    float* dst = g_dt + (long)z*DI*LL;
    #pragma unroll 4
    for (int jj=0;jj<16;jj++){
        int tl = tg + 16*jj;
        float xv[8];
        #pragma unroll
        for (int r=0;r<8;r++) xv[r] = sB[r][tl];
        #pragma unroll
        for (int i=0;i<4;i++){
            float a = bs[i];
            #pragma unroll
            for (int r=0;r<8;r++) a += w[i][r]*xv[r];
            float sp = fmaxf(a,0.f) + log1pf(__expf(-fabsf(a)));
            dst[(long)(d0+dgrp*4+i)*LL + t0+tl] = sp;
        }
    }
}

// ======================= chunked selective scan ==============================
// Phase A: per-chunk local scan from h=0 -> g_hloc, plus per-chunk sum(dt).
__global__ void k_scan1(const float* __restrict__ A_log)
{
    int z = blockIdx.z;
    int dir = (z%6)>>1;
    int d0 = blockIdx.y*32;
    int ch = blockIdx.x, c0 = ch*CHL;
    int tid = threadIdx.x;
    int lane = tid&31, warp = tid>>5;
    int ngrp = lane&3;
    int dl = warp*8 + (lane>>2);
    int d = d0+dl;
    float An[4];
    #pragma unroll
    for (int i=0;i<4;i++)
        An[i] = -__expf(A_log[(long)(dir*DI+d)*DS + ngrp*4+i]);

    const float* dtB = g_dt     + (long)z*DI*LL;
    const float* xB  = g_xcv_dm + (long)z*DI*LL;
    const float* dblT= g_dblT   + (long)z*40*LL;

    __shared__ float s_dt[32][129], s_x[32][129];
    __shared__ float s_B[128][16];

    for (int f4=tid; f4<1024; f4+=128){
        int r = f4>>5, c4 = (f4&31)*4;
        float4 v = *(const float4*)(dtB + (long)(d0+r)*LL + c0 + c4);
        s_dt[r][c4+0]=v.x; s_dt[r][c4+1]=v.y; s_dt[r][c4+2]=v.z; s_dt[r][c4+3]=v.w;
        float4 w = *(const float4*)(xB + (long)(d0+r)*LL + c0 + c4);
        s_x[r][c4+0]=w.x; s_x[r][c4+1]=w.y; s_x[r][c4+2]=w.z; s_x[r][c4+3]=w.w;
    }
    for (int f4=tid; f4<512; f4+=128){
        int n = f4>>5, tc = (f4&31)*4;
        float4 v = *(const float4*)(dblT + (long)(8+n)*LL + c0 + tc);
        s_B[tc+0][n]=v.x; s_B[tc+1][n]=v.y; s_B[tc+2][n]=v.z; s_B[tc+3][n]=v.w;
    }
    __syncthreads();

    float h0=0.f,h1=0.f,h2=0.f,h3=0.f, sdt=0.f;
    #pragma unroll 4
    for (int t=0;t<CHL;t++){
        float dtv = s_dt[dl][t];
        float xv  = s_x[dl][t];
        sdt += dtv;
        float4 Bv = *(const float4*)&s_B[t][ngrp*4];
        float bs = dtv*xv;
        h0 = __expf(dtv*An[0])*h0 + bs*Bv.x;
        h1 = __expf(dtv*An[1])*h1 + bs*Bv.y;
        h2 = __expf(dtv*An[2])*h2 + bs*Bv.z;
        h3 = __expf(dtv*An[3])*h3 + bs*Bv.w;
    }
    long base = ((long)(z*NCH+ch)*DI + d)*DS;
    *(float4*)(g_hloc + base + ngrp*4) = make_float4(h0,h1,h2,h3);
    if (ngrp==0) g_sdt[(long)(z*NCH+ch)*DI + d] = sdt;
}

// Phase B: compose chunk states serially (32 steps per (z,d,n))
__global__ void k_scan2(const float* __restrict__ A_log)
{
    int i = blockIdx.x*256 + threadIdx.x;      // 0..49151
    int z = i>>12, rem = i&4095;
    int d = rem>>4, n = rem&15;
    int dir = (z%6)>>1;
    float An = -__expf(A_log[(long)(dir*DI + d)*DS + n]);
    float h = 0.f;
    #pragma unroll 4
    for (int c=0;c<NCH;c++){
        long base = (long)(z*NCH+c)*DI + d;
        g_hin[base*DS + n] = h;
        float S = g_sdt[base];
        h = __expf(An*S)*h + g_hloc[base*DS + n];
    }
}

// Phase C: per-chunk full scan with y, from composed h_in.
__global__ void k_scan3(const float* __restrict__ A_log, const float* __restrict__ Dp)
{
    int z = blockIdx.z;
    int dir = (z%6)>>1;
    int d0 = blockIdx.y*32;
    int ch = blockIdx.x, c0 = ch*CHL;
    int tid = threadIdx.x;
    int lane = tid&31, warp = tid>>5;
    int ngrp = lane&3;
    int dl = warp*8 + (lane>>2);
    int d = d0+dl;
    float An[4];
    #pragma unroll
    for (int i=0;i<4;i++)
        An[i] = -__expf(A_log[(long)(dir*DI+d)*DS + ngrp*4+i]);

    const float* dtB = g_dt     + (long)z*DI*LL;
    const float* xB  = g_xcv_dm + (long)z*DI*LL;
    const float* dblT= g_dblT   + (long)z*40*LL;
    const float* zB  = xz_base(z) + (long)DI*LL;
    float* yB = g_ydir + (long)z*DI*LL;

    __shared__ float s_dt[32][129], s_x[32][129];   // s_dt rows become y
    __shared__ float s_B[64][16], s_C[64][16];

    for (int f4=tid; f4<1024; f4+=128){
        int r = f4>>5, c4 = (f4&31)*4;
        float4 v = *(const float4*)(dtB + (long)(d0+r)*LL + c0 + c4);
        s_dt[r][c4+0]=v.x; s_dt[r][c4+1]=v.y; s_dt[r][c4+2]=v.z; s_dt[r][c4+3]=v.w;
        float4 w = *(const float4*)(xB + (long)(d0+r)*LL + c0 + c4);
        s_x[r][c4+0]=w.x; s_x[r][c4+1]=w.y; s_x[r][c4+2]=w.z; s_x[r][c4+3]=w.w;
    }
    long hbase = ((long)(z*NCH+ch)*DI + d)*DS;
    float4 hv = *(const float4*)(g_hin + hbase + ngrp*4);
    float h0=hv.x, h1=hv.y, h2=hv.z, h3=hv.w;

    #pragma unroll
    for (int half=0; half<2; half++){
        __syncthreads();
        for (int f4=tid; f4<256; f4+=128){
            int n = f4>>4, tc = (f4&15)*4;
            float4 v = *(const float4*)(dblT + (long)(8+n)*LL  + c0 + half*64 + tc);
            s_B[tc+0][n]=v.x; s_B[tc+1][n]=v.y; s_B[tc+2][n]=v.z; s_B[tc+3][n]=v.w;
            float4 w = *(const float4*)(dblT + (long)(24+n)*LL + c0 + half*64 + tc);
            s_C[tc+0][n]=w.x; s_C[tc+1][n]=w.y; s_C[tc+2][n]=w.z; s_C[tc+3][n]=w.w;
        }
        __syncthreads();
        int tbase = half*64;
        #pragma unroll 4
        for (int tt=0; tt<64; tt++){
            int t = tbase+tt;
            float dtv = s_dt[dl][t];
            float xv  = s_x[dl][t];
            float4 Bv = *(const float4*)&s_B[tt][ngrp*4];
            float4 Cv = *(const float4*)&s_C[tt][ngrp*4];
            float bs = dtv*xv;
            h0 = __expf(dtv*An[0])*h0 + bs*Bv.x;
            h1 = __expf(dtv*An[1])*h1 + bs*Bv.y;
            h2 = __expf(dtv*An[2])*h2 + bs*Bv.z;
            h3 = __expf(dtv*An[3])*h3 + bs*Bv.w;
            float p = h0*Cv.x + h1*Cv.y + h2*Cv.z + h3*Cv.w;
            p += __shfl_xor_sync(0xffffffffu, p, 1);
            p += __shfl_xor_sync(0xffffffffu, p, 2);
            if (ngrp==0) s_dt[dl][t] = p;     // dt(t) already consumed
        }
    }
    __syncthreads();
    for (int k=0;k<32;k++){
        int r = k, cc = tid;
        float zv = zB[(long)(d0+r)*LL + c0+cc];
        float sz = zv / (1.f + __expf(-zv));
        float yv = (s_dt[r][cc] + Dp[dir*DI+d0+r]*s_x[r][cc]) * sz;
        yB[(long)(d0+r)*LL + c0+cc] = yv;
    }
}

// ---------------- combine 3 directions (fwd + flip + 64x64 transpose) ---------
__global__ void k_combine()
{
    int z2 = blockIdx.z, d = blockIdx.y;
    int f = z2>>1, b = z2&1;
    long off0 = ((long)((f*3+0)*2+b)*DI + d)*LL;
    long off1 = ((long)((f*3+1)*2+b)*DI + d)*LL;
    long off2 = ((long)((f*3+2)*2+b)*DI + d)*LL;
    long offo = ((long)z2*DI + d)*LL;
    int i0 = (blockIdx.x&1)*32, j0 = (blockIdx.x>>1)*32;
    int tx=threadIdx.x, ty=threadIdx.y;
    __shared__ float s[32][33];
    #pragma unroll
    for (int r=0;r<4;r++){
        int jj = ty+8*r;
        s[jj][tx] = g_ydir[off2 + (j0+jj)*64 + i0+tx];
    }
    __syncthreads();
    #pragma unroll
    for (int r=0;r<4;r++){
        int ii = ty+8*r;
        int l = (i0+ii)*64 + j0+tx;
        g_ycomb[offo + l] = g_ydir[off0 + l] + g_ydir[off1 + (LL-1-l)] + s[tx][ii];
    }
}

// ---------------- res[c][l] -> out flat (l*128 + c), via tile transpose -------
__global__ void k_resremap(float* __restrict__ outp)
{
    int b = blockIdx.z, c0 = blockIdx.y*32, l0 = blockIdx.x*32;
    int tx=threadIdx.x, ty=threadIdx.y;
    __shared__ float s[32][33];
    #pragma unroll
    for (int r=0;r<4;r++){
        int cl = ty+8*r;
        s[cl][tx] = g_res[(long)b*DM*LL + (long)(c0+cl)*LL + l0+tx];
    }
    __syncthreads();
    #pragma unroll
    for (int r=0;r<4;r++){
        int ll = ty+8*r;
        outp[(long)b*DM*LL + (long)(l0+ll)*DM + c0+tx] = s[tx][ll];
    }
}

// ---------------- batchnorm over (b,h,w) per channel --------------------------
__global__ void k_bnstats(const float* __restrict__ outp)
{
    int cc = blockIdx.x, tid = threadIdx.x;
    __shared__ float ss[256], sq[256];
    float a=0.f, q=0.f;
    for (int i=tid;i<2*LL;i+=256){
        float v = outp[(long)(i>>12)*DM*LL + (long)cc*LL + (i&(LL-1))];
        a+=v; q+=v*v;
    }
    ss[tid]=a; sq[tid]=q;
    __syncthreads();
    for (int st=128; st>0; st>>=1){
        if (tid<st){ ss[tid]+=ss[tid+st]; sq[tid]+=sq[tid+st]; }
        __syncthreads();
    }
    if (tid==0){
        float mu = ss[0]*(1.f/(2*LL));
        float var = sq[0]*(1.f/(2*LL)) - mu*mu;
        g_bnmu[cc]=mu; g_bnrv[cc]=rsqrtf(var+EPS);
    }
}

__global__ void k_bnapply(float* __restrict__ outp, const float* __restrict__ bg,
                          const float* __restrict__ bb)
{
    long gi = (long)blockIdx.x*256 + threadIdx.x;
    int cc = (int)((gi>>12)&127);
    outp[gi] = (outp[gi]-g_bnmu[cc])*g_bnrv[cc]*bg[cc] + bb[cc];
}

// ---------------- launcher ----------------------------------------------------
extern "C" void kernel_launch(void* const* d_in, const int* in_sizes, int n_in,
                              void* d_out, int out_size)
{
    const float* x1        = (const float*)d_in[0];
    const float* x2        = (const float*)d_in[1];
    const float* ln_g      = (const float*)d_in[2];
    const float* ln_b      = (const float*)d_in[3];
    const float* in_proj_w = (const float*)d_in[4];
    const float* conv_w    = (const float*)d_in[5];
    const float* conv_b    = (const float*)d_in[6];
    const float* xproj_w   = (const float*)d_in[7];
    const float* dtproj_w  = (const float*)d_in[8];
    const float* dtproj_b  = (const float*)d_in[9];
    const float* A_log     = (const float*)d_in[10];
    const float* Dvec      = (const float*)d_in[11];
    const float* out_proj_w= (const float*)d_in[12];
    const float* bn_g      = (const float*)d_in[13];
    const float* bn_b      = (const float*)d_in[14];
    float* outp = (float*)d_out;

    float *p_xn,*p_xz,*p_dm,*p_dblT,*p_ycomb,*p_feat,*p_dpp,*p_dp,*p_res;
    cudaGetSymbolAddress((void**)&p_xn,   g_xn);
    cudaGetSymbolAddress((void**)&p_xz,   g_xz);
    cudaGetSymbolAddress((void**)&p_dm,   g_xcv_dm);
    cudaGetSymbolAddress((void**)&p_dblT, g_dblT);
    cudaGetSymbolAddress((void**)&p_ycomb,g_ycomb);
    cudaGetSymbolAddress((void**)&p_feat, g_feat);
    cudaGetSymbolAddress((void**)&p_dpp,  g_dpp);
    cudaGetSymbolAddress((void**)&p_dp,   g_dp);
    cudaGetSymbolAddress((void**)&p_res,  g_res);

    dim3 blk8(32,8);

    // 1. layernorm -> xn[f,b,l,c]
    k_ln<<<dim3(128,2,2),256>>>(x1,x2,ln_g,ln_b);
    // 2. in_proj (NT, tf32): xz[fb][d2][l] = W(512x128) * xn[fb]^T
    tgemm_nt<<<dim3(32,8,4),256>>>(in_proj_w, p_xn, p_xz,
        512,4096,128, 128,128,4096,
        0L,1,1, (long)LL*DM,1,4, (long)512*LL);
    // 3. direction remap (dirs 1,2 only)
    k_remap<<<dim3(4,512,8),256>>>();
    // 4. causal conv + silu -> xcv_dm[z][d][t]
    k_conv<<<dim3(4,256,12),256>>>(conv_w, conv_b);
    // 5. xproj (NN, tf32): dblT[z][r][t] = xpw(40x256) * xcv_dm[z](256x4096)
    tgemm_nn<<<dim3(32,1,12),256>>>(xproj_w, p_dm, p_dblT,
        40,4096,256, 256,4096,4096,
        40L*DI,2,3, (long)DI*LL,1,12, 40L*LL);
    // 6. dt projection + softplus (smem-staged)
    k_dtproj<<<dim3(16,4,12),256>>>(dtproj_w, dtproj_b);
    // 7. chunked selective scan: local -> compose -> final
    k_scan1<<<dim3(NCH,8,12),128>>>(A_log);
    k_scan2<<<192,256>>>(A_log);
    k_scan3<<<dim3(NCH,8,12),128>>>(A_log, Dvec);
    // 8. combine 3 directions
    k_combine<<<dim3(4,256,4),blk8>>>();
    // 9. out_proj (NN, tf32): feat[fb][c][l] = opw(128x256) * ycomb[fb]
    tgemm_nn<<<dim3(32,2,4),256>>>(out_proj_w, p_ycomb, p_feat,
        128,4096,256, 256,4096,4096,
        0L,1,1, (long)DI*LL,1,4, (long)DM*LL);
    // 10. dp split-K (32 chunks, fp32) + deterministic reduce
    k_dp<<<dim3(2,2,64),256>>>(p_feat, p_dpp);
    k_dpred<<<128,256>>>();
    // 11. res (NN, tf32): res[b][c][l] = dp[b](128x128) * Bf[b]
    tgemm_nn<<<dim3(32,2,2),256>>>(p_dp, p_feat + 2L*DM*LL, p_res,
        128,4096,128, 128,4096,4096,
        (long)DM*DM,1,2, (long)DM*LL,1,2, (long)DM*LL);
    // 12. remap res -> out layout (b, c', h, w) == flat (l*128 + c)
    k_resremap<<<dim3(128,4,2),blk8>>>(outp);
    // 13-14. batchnorm over (b,h,w)
    k_bnstats<<<128,256>>>(outp);
    k_bnapply<<<4096,256>>>(outp, bn_g, bn_b);
}